// round 2
// baseline (speedup 1.0000x reference)
#include <cuda_runtime.h>
#include <math.h>
#include <float.h>

#define DE 256
#define MAXN 50000
#define MAXE 800000
#define MAXG 256

static __device__ int   g_deg[MAXN];
static __device__ int   g_rowptr[MAXN + 1];
static __device__ int   g_cursor[MAXN + 1];
static __device__ int   g_col[MAXE];
static __device__ int   g_gcnt[MAXG];
static __device__ int   g_gptr[MAXG + 1];
static __device__ float g_agg[MAXN * 256];
static __device__ float g_tmp[MAXN * 256];
static __device__ float g_hc[(size_t)MAXN * 1024];
static __device__ float g_pool[MAXG * 1024];

// ---------------------------------------------------------------- utilities
__global__ void k_zero(int N, int G) {
    int i = blockIdx.x * blockDim.x + threadIdx.x;
    if (i < N) g_deg[i] = 0;
    if (i < G) g_gcnt[i] = 0;
}

__device__ __forceinline__ int clampi(int v, int n) {
    return v < 0 ? 0 : (v >= n ? n - 1 : v);
}

__global__ void k_hist_edges(const int* __restrict__ ei, int E, int N) {
    int e = blockIdx.x * blockDim.x + threadIdx.x;
    if (e < E) atomicAdd(&g_deg[clampi(ei[E + e], N)], 1);   // dst histogram
}

__global__ void k_hist_nodes(const int* __restrict__ batch, int N, int G) {
    int i = blockIdx.x * blockDim.x + threadIdx.x;
    if (i < N) atomicAdd(&g_gcnt[clampi(batch[i], G)], 1);
}

// single-block exclusive scan (n <= ~64k); writes out[0..n] and out2[0..n]
__global__ void k_scan(const int* __restrict__ in, int* __restrict__ out,
                       int* __restrict__ out2, int n) {
    __shared__ int wsum[32];
    int tid = threadIdx.x;
    int chunk = (n + blockDim.x - 1) / blockDim.x;
    int s = tid * chunk;
    int e = min(s + chunk, n);
    int local = 0;
    for (int i = s; i < e; i++) local += in[i];
    int lane = tid & 31, wid = tid >> 5;
    int v = local;
#pragma unroll
    for (int o = 1; o < 32; o <<= 1) {
        int t = __shfl_up_sync(0xffffffffu, v, o);
        if (lane >= o) v += t;
    }
    if (lane == 31) wsum[wid] = v;
    __syncthreads();
    if (wid == 0) {
        int nw = blockDim.x >> 5;
        int w = (lane < nw) ? wsum[lane] : 0;
#pragma unroll
        for (int o = 1; o < 32; o <<= 1) {
            int t = __shfl_up_sync(0xffffffffu, w, o);
            if (lane >= o) w += t;
        }
        wsum[lane] = w;
    }
    __syncthreads();
    int excl = v - local + (wid ? wsum[wid - 1] : 0);
    int run = excl;
    for (int i = s; i < e; i++) {
        out[i] = run;
        out2[i] = run;
        run += in[i];
    }
    if (s < n && e == n) { out[n] = run; out2[n] = run; }
}

__global__ void k_scatter(const int* __restrict__ ei, int E, int N) {
    int e = blockIdx.x * blockDim.x + threadIdx.x;
    if (e < E) {
        int d = clampi(ei[E + e], N);
        int p = atomicAdd(&g_cursor[d], 1);
        if (p < MAXE) g_col[p] = clampi(ei[e], N);  // store src, binned by dst
    }
}

// -------------------------------------------------------------- aggregation
// one warp per destination node; register-resident max over CSR neighbors
__device__ __forceinline__ float4 fmax4(float4 a, float4 b) {
    return make_float4(fmaxf(a.x, b.x), fmaxf(a.y, b.y),
                       fmaxf(a.z, b.z), fmaxf(a.w, b.w));
}

__global__ void k_agg(const float* __restrict__ h, int ldh, int din,
                      float* __restrict__ out, int ldo, int N) {
    int w = (blockIdx.x * blockDim.x + threadIdx.x) >> 5;
    int lane = threadIdx.x & 31;
    if (w >= N) return;
    int s = g_rowptr[w], e = g_rowptr[w + 1];
    float4 m0 = make_float4(-FLT_MAX, -FLT_MAX, -FLT_MAX, -FLT_MAX);
    float4 m1 = m0;
    if (din == 256) {
        for (int j = s; j < e; j++) {
            const float4* r = (const float4*)(h + (size_t)g_col[j] * ldh);
            float4 v0 = r[lane];
            float4 v1 = r[lane + 32];
            m0 = fmax4(m0, v0);
            m1 = fmax4(m1, v1);
        }
    } else {  // din == 128
        for (int j = s; j < e; j++) {
            const float4* r = (const float4*)(h + (size_t)g_col[j] * ldh);
            m0 = fmax4(m0, r[lane]);
        }
    }
    if (e == s) { m0 = make_float4(0.f, 0.f, 0.f, 0.f); m1 = m0; }
    float4* o = (float4*)(out + (size_t)w * ldo);
    o[lane] = m0;
    if (din == 256) o[lane + 32] = m1;
}

// -------------------------------------------------------------------- GEMM
// C[M,256] = (A1[:, :K1] @ W1) + (A2[:, :K2] @ W2) + bias, optional relu.
// W row-major [K,256]. Tile 128x128x16, 256 threads, 8x8 per thread,
// double-buffered shared memory.
__global__ __launch_bounds__(256, 2)
void k_gemm(const float* __restrict__ A1, int lda1,
            const float* __restrict__ W1, int K1,
            const float* __restrict__ A2, int lda2,
            const float* __restrict__ W2, int K2,
            const float* __restrict__ bias,
            float* __restrict__ C, int ldc, int M, int doRelu) {
    __shared__ float As[2][128][20];   // [m][k] padded row (float4-aligned)
    __shared__ float Bs[2][16][128];

    const int tid = threadIdx.x;
    const int tx = tid & 15, ty = tid >> 4;
    const int m0 = blockIdx.x * 128, n0 = blockIdx.y * 128;
    const int arow = tid >> 2;           // 0..63
    const int akc = (tid & 3) << 2;      // 0,4,8,12
    const int brow = tid >> 5;           // 0..7
    const int bcol = (tid & 31) << 2;    // 0..124
    const int t1 = K1 >> 4;
    const int nt = t1 + (K2 >> 4);

    float acc[8][8];
#pragma unroll
    for (int i = 0; i < 8; i++)
#pragma unroll
        for (int j = 0; j < 8; j++) acc[i][j] = 0.f;

    float4 a0, a1, b0, b1;

    auto fetch = [&](int t) {
        const float* A; const float* W; int lda, kt;
        if (t < t1) { A = A1; W = W1; lda = lda1; kt = t << 4; }
        else        { A = A2; W = W2; lda = lda2; kt = (t - t1) << 4; }
        int r0 = m0 + arow;
        int r1 = r0 + 64;
        a0 = (r0 < M) ? *(const float4*)(A + (size_t)r0 * lda + kt + akc)
                      : make_float4(0.f, 0.f, 0.f, 0.f);
        a1 = (r1 < M) ? *(const float4*)(A + (size_t)r1 * lda + kt + akc)
                      : make_float4(0.f, 0.f, 0.f, 0.f);
        b0 = *(const float4*)(W + (size_t)(kt + brow) * 256 + n0 + bcol);
        b1 = *(const float4*)(W + (size_t)(kt + brow + 8) * 256 + n0 + bcol);
    };
    auto stage = [&](int buf) {
        *(float4*)&As[buf][arow][akc] = a0;
        *(float4*)&As[buf][arow + 64][akc] = a1;
        *(float4*)&Bs[buf][brow][bcol] = b0;
        *(float4*)&Bs[buf][brow + 8][bcol] = b1;
    };

    fetch(0);
    stage(0);
    __syncthreads();

    for (int t = 0; t < nt; t++) {
        int buf = t & 1;
        bool more = (t + 1 < nt);
        if (more) fetch(t + 1);
#pragma unroll
        for (int kk = 0; kk < 16; kk++) {
            float a[8], bb[8];
#pragma unroll
            for (int i = 0; i < 8; i++) a[i] = As[buf][ty * 8 + i][kk];
            float4 bv0 = *(const float4*)&Bs[buf][kk][tx * 8];
            float4 bv1 = *(const float4*)&Bs[buf][kk][tx * 8 + 4];
            bb[0] = bv0.x; bb[1] = bv0.y; bb[2] = bv0.z; bb[3] = bv0.w;
            bb[4] = bv1.x; bb[5] = bv1.y; bb[6] = bv1.z; bb[7] = bv1.w;
#pragma unroll
            for (int i = 0; i < 8; i++)
#pragma unroll
                for (int j = 0; j < 8; j++)
                    acc[i][j] = fmaf(a[i], bb[j], acc[i][j]);
        }
        if (more) stage(buf ^ 1);
        __syncthreads();
    }

#pragma unroll
    for (int i = 0; i < 8; i++) {
        int r = m0 + ty * 8 + i;
        if (r >= M) continue;
#pragma unroll
        for (int j = 0; j < 8; j += 4) {
            int c = n0 + tx * 8 + j;
            float4 v;
            v.x = acc[i][j + 0] + bias[c + 0];
            v.y = acc[i][j + 1] + bias[c + 1];
            v.z = acc[i][j + 2] + bias[c + 2];
            v.w = acc[i][j + 3] + bias[c + 3];
            if (doRelu) {
                v.x = fmaxf(v.x, 0.f); v.y = fmaxf(v.y, 0.f);
                v.z = fmaxf(v.z, 0.f); v.w = fmaxf(v.w, 0.f);
            }
            *(float4*)(C + (size_t)r * ldc + c) = v;
        }
    }
}

// -------------------------------------------------------------------- pool
__global__ void k_pool() {
    int b = blockIdx.x;
    int f = blockIdx.y * 256 + threadIdx.x;
    int s = g_gptr[b], e = g_gptr[b + 1];
    float m = -FLT_MAX;
    int n = s;
    for (; n + 3 < e; n += 4) {
        float v0 = g_hc[(size_t)(n + 0) * 1024 + f];
        float v1 = g_hc[(size_t)(n + 1) * 1024 + f];
        float v2 = g_hc[(size_t)(n + 2) * 1024 + f];
        float v3 = g_hc[(size_t)(n + 3) * 1024 + f];
        m = fmaxf(m, fmaxf(fmaxf(v0, v1), fmaxf(v2, v3)));
    }
    for (; n < e; n++) m = fmaxf(m, g_hc[(size_t)n * 1024 + f]);
    g_pool[b * 1024 + f] = (e > s) ? m : 0.f;
}

// -------------------------------------------------------------------- head
__global__ void k_head(const float* __restrict__ W1, const float* __restrict__ b1,
                       const float* __restrict__ W2, const float* __restrict__ b2,
                       float* __restrict__ outbuf, int G, int DT) {
    __shared__ float sg[1024];
    __shared__ float sl[256];
    __shared__ float so[32];
    __shared__ float slse;
    int b = blockIdx.x, t = threadIdx.x;
    for (int k = t; k < 1024; k += 256) sg[k] = g_pool[b * 1024 + k];
    __syncthreads();
    float acc = b1[t];
#pragma unroll 4
    for (int k = 0; k < 1024; k++) acc = fmaf(sg[k], W1[k * 256 + t], acc);
    acc = fmaxf(acc, 0.f);
    sl[t] = acc;
    outbuf[2 * G * DT + b * 256 + t] = acc;     // last_layer
    __syncthreads();
    if (t < DT) {
        float o = b2[t];
        for (int k = 0; k < 256; k++) o = fmaf(sl[k], W2[k * DT + t], o);
        so[t] = o;
    }
    __syncthreads();
    if (t == 0) {
        float mx = -FLT_MAX;
        for (int j = 0; j < DT; j++) mx = fmaxf(mx, so[j]);
        float s2 = 0.f;
        for (int j = 0; j < DT; j++) s2 += expf(so[j] - mx);
        slse = mx + logf(s2);
    }
    __syncthreads();
    if (t < DT) {
        outbuf[b * DT + t] = so[t] - slse;      // log_softmax
        outbuf[G * DT + b * DT + t] = so[t];    // raw logits
    }
}

// ------------------------------------------------------------------ launch
extern "C" void kernel_launch(void* const* d_in, const int* in_sizes, int n_in,
                              void* d_out, int out_size) {
    const float* x = (const float*)d_in[0];
    const int* ei = (const int*)d_in[1];       // int32 (JAX default config)
    const int* batch = (const int*)d_in[2];    // int32
    const float *Wl[4], *bl[4], *Wr[4], *Wm[4], *bm[4];
    int p = 3;
    for (int l = 0; l < 4; l++) {
        Wl[l] = (const float*)d_in[p++];
        bl[l] = (const float*)d_in[p++];
        Wr[l] = (const float*)d_in[p++];
        Wm[l] = (const float*)d_in[p++];
        bm[l] = (const float*)d_in[p++];
    }
    const float* fc1W = (const float*)d_in[p++];
    const float* fc1b = (const float*)d_in[p++];
    const float* fc2W = (const float*)d_in[p++];
    const float* fc2b = (const float*)d_in[p++];

    int N = in_sizes[0] / 128;
    int E = in_sizes[1] / 2;
    int DT = in_sizes[26];                 // fc2_b element count
    int G = out_size / (2 * DT + DE);

    float *agg, *tmp, *hc;
    int *deg, *rowptr, *cursor, *gcnt, *gptr;
    cudaGetSymbolAddress((void**)&agg, g_agg);
    cudaGetSymbolAddress((void**)&tmp, g_tmp);
    cudaGetSymbolAddress((void**)&hc, g_hc);
    cudaGetSymbolAddress((void**)&deg, g_deg);
    cudaGetSymbolAddress((void**)&rowptr, g_rowptr);
    cudaGetSymbolAddress((void**)&cursor, g_cursor);
    cudaGetSymbolAddress((void**)&gcnt, g_gcnt);
    cudaGetSymbolAddress((void**)&gptr, g_gptr);

    int mx = (N > G) ? N : G;
    k_zero<<<(mx + 255) / 256, 256>>>(N, G);
    k_hist_edges<<<(E + 255) / 256, 256>>>(ei, E, N);
    k_hist_nodes<<<(N + 255) / 256, 256>>>(batch, N, G);
    k_scan<<<1, 1024>>>(deg, rowptr, cursor, N);
    k_scan<<<1, 1024>>>(gcnt, gptr, gptr, G);
    k_scatter<<<(E + 255) / 256, 256>>>(ei, E, N);

    for (int l = 0; l < 4; l++) {
        const float* h = l ? (hc + (l - 1) * DE) : x;
        int ldh = l ? 1024 : 128;
        int din = l ? 256 : 128;
        k_agg<<<(N * 32 + 255) / 256, 256>>>(h, ldh, din, agg, din, N);
        dim3 gg((N + 127) / 128, 2);
        k_gemm<<<gg, 256>>>(agg, din, Wl[l], din, h, ldh, Wr[l], din,
                            bl[l], tmp, 256, N, 0);
        k_gemm<<<gg, 256>>>(tmp, 256, Wm[l], 256, nullptr, 0, nullptr, 0,
                            bm[l], hc + l * DE, 1024, N, 1);
    }
    k_pool<<<dim3(G, 4), 256>>>();
    k_head<<<G, 256>>>(fc1W, fc1b, fc2W, fc2b, (float*)d_out, G, DT);
}

// round 4
// speedup vs baseline: 1.8702x; 1.8702x over previous
#include <cuda_runtime.h>
#include <cuda_bf16.h>
#include <math.h>
#include <float.h>

#define DE 256
#define MAXN 50000
#define MAXG 256
#define MAXE 800000

// ------------------------------------------------------------- scratch
static __device__ int   g_deg[MAXN];
static __device__ int   g_rowptr[MAXN + 1];
static __device__ int   g_cursor[MAXN + 1];
static __device__ int   g_col[MAXE];
static __device__ int   g_gcnt[MAXG];
static __device__ int   g_gptr[MAXG + 1];
static __device__ int   g_part[512];
static __device__ float g_agg[MAXN * 256];
static __device__ float g_tmp[MAXN * 256];
static __device__ float g_hc[(size_t)MAXN * 1024];
static __device__ float g_pool[MAXG * 1024];

// ---------------------------------------------------------------- utilities
__global__ void k_zero(int N, int G) {
    int i = blockIdx.x * blockDim.x + threadIdx.x;
    if (i < N) g_deg[i] = 0;
    if (i < G) g_gcnt[i] = 0;
}
__device__ __forceinline__ int clampi(int v, int n) {
    return v < 0 ? 0 : (v >= n ? n - 1 : v);
}
__global__ void k_hist_edges(const int* __restrict__ ei, int E, int N) {
    int e = blockIdx.x * blockDim.x + threadIdx.x;
    if (e < E) atomicAdd(&g_deg[clampi(ei[E + e], N)], 1);
}
__global__ void k_hist_nodes(const int* __restrict__ batch, int N, int G) {
    int i = blockIdx.x * blockDim.x + threadIdx.x;
    if (i < N) atomicAdd(&g_gcnt[clampi(batch[i], G)], 1);
}

// three-phase multi-block exclusive scan
__global__ void k_scan_blk(const int* __restrict__ in, int* __restrict__ out, int n) {
    __shared__ int ws[8], wsx[8];
    int i = blockIdx.x * 256 + threadIdx.x;
    int v = (i < n) ? in[i] : 0;
    int lane = threadIdx.x & 31, w = threadIdx.x >> 5;
    int inc = v;
#pragma unroll
    for (int o = 1; o < 32; o <<= 1) {
        int t = __shfl_up_sync(0xffffffffu, inc, o);
        if (lane >= o) inc += t;
    }
    if (lane == 31) ws[w] = inc;
    __syncthreads();
    if (threadIdx.x == 0) {
        int run = 0;
#pragma unroll
        for (int j = 0; j < 8; j++) { int t = ws[j]; wsx[j] = run; run += t; }
        g_part[blockIdx.x] = run;
    }
    __syncthreads();
    if (i < n) out[i] = inc - v + wsx[w];
}
__global__ void k_scan_top(int nb, int* outA, int* outB, int n) {
    __shared__ int ws[8], wsx[8];
    int tid = threadIdx.x;
    int v = (tid < nb) ? g_part[tid] : 0;
    int lane = tid & 31, w = tid >> 5;
    int inc = v;
#pragma unroll
    for (int o = 1; o < 32; o <<= 1) {
        int t = __shfl_up_sync(0xffffffffu, inc, o);
        if (lane >= o) inc += t;
    }
    if (lane == 31) ws[w] = inc;
    __syncthreads();
    if (tid == 0) {
        int run = 0;
#pragma unroll
        for (int j = 0; j < 8; j++) { int t = ws[j]; wsx[j] = run; run += t; }
        outA[n] = run; outB[n] = run;
    }
    __syncthreads();
    int excl = inc - v + wsx[w];
    __syncthreads();
    if (tid < nb) g_part[tid] = excl;
}
__global__ void k_scan_add(int* __restrict__ out, int* __restrict__ out2, int n) {
    int i = blockIdx.x * 256 + threadIdx.x;
    if (i < n) { int v = out[i] + g_part[blockIdx.x]; out[i] = v; out2[i] = v; }
}

// single-block scan for the small G histogram
__global__ void k_scan(const int* __restrict__ in, int* __restrict__ out,
                       int* __restrict__ out2, int n) {
    __shared__ int wsum[32];
    int tid = threadIdx.x;
    int chunk = (n + blockDim.x - 1) / blockDim.x;
    int s = tid * chunk, e = min(s + chunk, n);
    int local = 0;
    for (int i = s; i < e; i++) local += in[i];
    int lane = tid & 31, wid = tid >> 5;
    int v = local;
#pragma unroll
    for (int o = 1; o < 32; o <<= 1) {
        int t = __shfl_up_sync(0xffffffffu, v, o);
        if (lane >= o) v += t;
    }
    if (lane == 31) wsum[wid] = v;
    __syncthreads();
    if (wid == 0) {
        int nw = blockDim.x >> 5;
        int w = (lane < nw) ? wsum[lane] : 0;
#pragma unroll
        for (int o = 1; o < 32; o <<= 1) {
            int t = __shfl_up_sync(0xffffffffu, w, o);
            if (lane >= o) w += t;
        }
        wsum[lane] = w;
    }
    __syncthreads();
    int excl = v - local + (wid ? wsum[wid - 1] : 0);
    int run = excl;
    for (int i = s; i < e; i++) { out[i] = run; out2[i] = run; run += in[i]; }
    if (s < n && e == n) { out[n] = run; out2[n] = run; }
}

__global__ void k_scatter(const int* __restrict__ ei, int E, int N) {
    int e = blockIdx.x * blockDim.x + threadIdx.x;
    if (e < E) {
        int d = clampi(ei[E + e], N);
        int p = atomicAdd(&g_cursor[d], 1);
        if (p < MAXE) g_col[p] = clampi(ei[e], N);
    }
}

// -------------------------------------------------------------- aggregation
__device__ __forceinline__ float4 fmax4(float4 a, float4 b) {
    return make_float4(fmaxf(a.x, b.x), fmaxf(a.y, b.y),
                       fmaxf(a.z, b.z), fmaxf(a.w, b.w));
}
__global__ void k_agg(const float* __restrict__ h, int ldh, int din,
                      float* __restrict__ out, int ldo, int N) {
    int w = (blockIdx.x * blockDim.x + threadIdx.x) >> 5;
    int lane = threadIdx.x & 31;
    if (w >= N) return;
    int s = g_rowptr[w], e = g_rowptr[w + 1];
    float4 m0 = make_float4(-FLT_MAX, -FLT_MAX, -FLT_MAX, -FLT_MAX);
    float4 m1 = m0;
    if (din == 256) {
        for (int j = s; j < e; j++) {
            const float4* r = (const float4*)(h + (size_t)g_col[j] * ldh);
            m0 = fmax4(m0, r[lane]);
            m1 = fmax4(m1, r[lane + 32]);
        }
    } else {
        for (int j = s; j < e; j++) {
            const float4* r = (const float4*)(h + (size_t)g_col[j] * ldh);
            m0 = fmax4(m0, r[lane]);
        }
    }
    if (e == s) { m0 = make_float4(0.f, 0.f, 0.f, 0.f); m1 = m0; }
    float4* o = (float4*)(out + (size_t)w * ldo);
    o[lane] = m0;
    if (din == 256) o[lane + 32] = m1;
}

// ------------------------------------------------------- mma.sync bf16 GEMM
// C[M,256] = [A1 | A2] @ [W1 ; W2] + bias (optional relu).
// fp32 emulated via bf16 hi/lo split: C = Ah*Bh + Ah*Bl + Al*Bh.
// CTA: 128(M) x 128(N), 8 warps of 64x32, K-chunk 32.
#define BSTR 40   // smem halves per row (32 data + 8 pad -> conflict-free)

__device__ __forceinline__ void pack_hilo(float f0, float f1,
                                          unsigned& hi, unsigned& lo) {
    __nv_bfloat16 h0 = __float2bfloat16(f0);
    __nv_bfloat16 h1 = __float2bfloat16(f1);
    float r0 = f0 - __bfloat162float(h0);
    float r1 = f1 - __bfloat162float(h1);
    __nv_bfloat16 l0 = __float2bfloat16(r0);
    __nv_bfloat16 l1 = __float2bfloat16(r1);
    hi = (unsigned)__bfloat16_as_ushort(h0) |
         ((unsigned)__bfloat16_as_ushort(h1) << 16);
    lo = (unsigned)__bfloat16_as_ushort(l0) |
         ((unsigned)__bfloat16_as_ushort(l1) << 16);
}

#define MMA_BF16(c, a0, a1, a2, a3, b0, b1)                                   \
    asm volatile(                                                             \
        "mma.sync.aligned.m16n8k16.row.col.f32.bf16.bf16.f32 "                \
        "{%0,%1,%2,%3}, {%4,%5,%6,%7}, {%8,%9}, {%0,%1,%2,%3};"               \
        : "+f"((c)[0]), "+f"((c)[1]), "+f"((c)[2]), "+f"((c)[3])              \
        : "r"(a0), "r"(a1), "r"(a2), "r"(a3), "r"(b0), "r"(b1))

__global__ __launch_bounds__(256, 2)
void k_gemm_mma(const float* __restrict__ A1, int lda1, int K0,
                const float* __restrict__ A2, int lda2, int K2,
                const float* __restrict__ W1, const float* __restrict__ W2,
                const float* __restrict__ bias,
                float* __restrict__ C, int ldc, int M, int doRelu) {
    __shared__ unsigned short As_h[128 * BSTR];
    __shared__ unsigned short As_l[128 * BSTR];
    __shared__ unsigned short Bs_h[128 * BSTR];
    __shared__ unsigned short Bs_l[128 * BSTR];

    const int tid = threadIdx.x;
    const int wid = tid >> 5, lane = tid & 31;
    const int lr = lane >> 2, lc = lane & 3;
    const int m0 = blockIdx.x * 128, n0 = blockIdx.y * 128;
    const int wm = (wid >> 2) * 64, wn = (wid & 3) * 32;
    const int K = K0 + K2;
    const int nc = K >> 5;

    float acc[4][4][4];
#pragma unroll
    for (int i = 0; i < 4; i++)
#pragma unroll
        for (int j = 0; j < 4; j++)
#pragma unroll
            for (int q = 0; q < 4; q++) acc[i][j][q] = 0.f;

    const int s_arow = tid >> 3;          // 0..31 (A staging row base)
    const int s_akq = (tid & 7) << 2;     // 0,4,..,28
    const int s_bn = tid & 127;           // B staging n
    const int s_bg = (tid >> 7) * 8;      // B staging k-pair group

    for (int t = 0; t < nc; t++) {
        int kb = t << 5;
        const float* Asel;
        const float* Wsel;
        int lda, kloc;
        if (kb < K0) { Asel = A1; Wsel = W1; lda = lda1; kloc = kb; }
        else         { Asel = A2; Wsel = W2; lda = lda2; kloc = kb - K0; }

        // stage A (128 x 32 fp32 -> bf16 hi/lo)
#pragma unroll
        for (int it = 0; it < 4; it++) {
            int row = s_arow + it * 32;
            int m = m0 + row;
            float4 v = make_float4(0.f, 0.f, 0.f, 0.f);
            if (m < M) v = *(const float4*)(Asel + (size_t)m * lda + kloc + s_akq);
            unsigned h0, l0, h1, l1;
            pack_hilo(v.x, v.y, h0, l0);
            pack_hilo(v.z, v.w, h1, l1);
            int idx = row * BSTR + s_akq;
            *(uint2*)&As_h[idx] = make_uint2(h0, h1);
            *(uint2*)&As_l[idx] = make_uint2(l0, l1);
        }
        // stage B transposed: smem[n][k] from W[k][n]
#pragma unroll
        for (int p = 0; p < 8; p++) {
            int kp = s_bg + p;
            int k0 = kloc + kp * 2;
            float f0 = Wsel[(size_t)k0 * 256 + n0 + s_bn];
            float f1 = Wsel[(size_t)(k0 + 1) * 256 + n0 + s_bn];
            unsigned hi, lo;
            pack_hilo(f0, f1, hi, lo);
            int idx = s_bn * BSTR + kp * 2;
            *(unsigned*)&Bs_h[idx] = hi;
            *(unsigned*)&Bs_l[idx] = lo;
        }
        __syncthreads();

#pragma unroll
        for (int ks = 0; ks < 32; ks += 16) {
            unsigned ah[4][4], al[4][4];
#pragma unroll
            for (int i = 0; i < 4; i++) {
                int r0 = (wm + i * 16 + lr) * BSTR + ks + lc * 2;
                int r8 = r0 + 8 * BSTR;
                ah[i][0] = *(const unsigned*)&As_h[r0];
                ah[i][1] = *(const unsigned*)&As_h[r8];
                ah[i][2] = *(const unsigned*)&As_h[r0 + 8];
                ah[i][3] = *(const unsigned*)&As_h[r8 + 8];
                al[i][0] = *(const unsigned*)&As_l[r0];
                al[i][1] = *(const unsigned*)&As_l[r8];
                al[i][2] = *(const unsigned*)&As_l[r0 + 8];
                al[i][3] = *(const unsigned*)&As_l[r8 + 8];
            }
#pragma unroll
            for (int j = 0; j < 4; j++) {
                int nb_ = (wn + j * 8 + lr) * BSTR + ks + lc * 2;
                unsigned bh0 = *(const unsigned*)&Bs_h[nb_];
                unsigned bh1 = *(const unsigned*)&Bs_h[nb_ + 8];
                unsigned bl0 = *(const unsigned*)&Bs_l[nb_];
                unsigned bl1 = *(const unsigned*)&Bs_l[nb_ + 8];
#pragma unroll
                for (int i = 0; i < 4; i++) {
                    MMA_BF16(acc[i][j], ah[i][0], ah[i][1], ah[i][2], ah[i][3], bh0, bh1);
                    MMA_BF16(acc[i][j], ah[i][0], ah[i][1], ah[i][2], ah[i][3], bl0, bl1);
                    MMA_BF16(acc[i][j], al[i][0], al[i][1], al[i][2], al[i][3], bh0, bh1);
                }
            }
        }
        __syncthreads();
    }

    // epilogue
#pragma unroll
    for (int i = 0; i < 4; i++) {
        int row0 = m0 + wm + i * 16 + lr;
#pragma unroll
        for (int j = 0; j < 4; j++) {
            int col = n0 + wn + j * 8 + lc * 2;
            float b0 = bias[col], b1 = bias[col + 1];
            float2 v0 = make_float2(acc[i][j][0] + b0, acc[i][j][1] + b1);
            float2 v1 = make_float2(acc[i][j][2] + b0, acc[i][j][3] + b1);
            if (doRelu) {
                v0.x = fmaxf(v0.x, 0.f); v0.y = fmaxf(v0.y, 0.f);
                v1.x = fmaxf(v1.x, 0.f); v1.y = fmaxf(v1.y, 0.f);
            }
            if (row0 < M)     *(float2*)(C + (size_t)row0 * ldc + col) = v0;
            if (row0 + 8 < M) *(float2*)(C + (size_t)(row0 + 8) * ldc + col) = v1;
        }
    }
}

// -------------------------------------------------------------------- pool
__global__ void k_pool() {
    int b = blockIdx.x;
    int f = blockIdx.y * 256 + threadIdx.x;
    int s = g_gptr[b], e = g_gptr[b + 1];
    float m = -FLT_MAX;
    int n = s;
    for (; n + 3 < e; n += 4) {
        float v0 = g_hc[(size_t)(n + 0) * 1024 + f];
        float v1 = g_hc[(size_t)(n + 1) * 1024 + f];
        float v2 = g_hc[(size_t)(n + 2) * 1024 + f];
        float v3 = g_hc[(size_t)(n + 3) * 1024 + f];
        m = fmaxf(m, fmaxf(fmaxf(v0, v1), fmaxf(v2, v3)));
    }
    for (; n < e; n++) m = fmaxf(m, g_hc[(size_t)n * 1024 + f]);
    g_pool[b * 1024 + f] = (e > s) ? m : 0.f;
}

// -------------------------------------------------------------------- head
__global__ void k_head(const float* __restrict__ W1, const float* __restrict__ b1,
                       const float* __restrict__ W2, const float* __restrict__ b2,
                       float* __restrict__ outbuf, int G, int DT) {
    __shared__ float sg[1024];
    __shared__ float sl[256];
    __shared__ float so[32];
    __shared__ float slse;
    int b = blockIdx.x, t = threadIdx.x;
    for (int k = t; k < 1024; k += 256) sg[k] = g_pool[b * 1024 + k];
    __syncthreads();
    float acc = b1[t];
#pragma unroll 4
    for (int k = 0; k < 1024; k++) acc = fmaf(sg[k], W1[k * 256 + t], acc);
    acc = fmaxf(acc, 0.f);
    sl[t] = acc;
    outbuf[2 * G * DT + b * 256 + t] = acc;
    __syncthreads();
    if (t < DT) {
        float o = b2[t];
        for (int k = 0; k < 256; k++) o = fmaf(sl[k], W2[k * DT + t], o);
        so[t] = o;
    }
    __syncthreads();
    if (t == 0) {
        float mx = -FLT_MAX;
        for (int j = 0; j < DT; j++) mx = fmaxf(mx, so[j]);
        float s2 = 0.f;
        for (int j = 0; j < DT; j++) s2 += expf(so[j] - mx);
        slse = mx + logf(s2);
    }
    __syncthreads();
    if (t < DT) {
        outbuf[b * DT + t] = so[t] - slse;
        outbuf[G * DT + b * DT + t] = so[t];
    }
}

// ------------------------------------------------------------------ launch
extern "C" void kernel_launch(void* const* d_in, const int* in_sizes, int n_in,
                              void* d_out, int out_size) {
    const float* x = (const float*)d_in[0];
    const int* ei = (const int*)d_in[1];
    const int* batch = (const int*)d_in[2];
    const float *Wl[4], *bl[4], *Wr[4], *Wm[4], *bm[4];
    int p = 3;
    for (int l = 0; l < 4; l++) {
        Wl[l] = (const float*)d_in[p++];
        bl[l] = (const float*)d_in[p++];
        Wr[l] = (const float*)d_in[p++];
        Wm[l] = (const float*)d_in[p++];
        bm[l] = (const float*)d_in[p++];
    }
    const float* fc1W = (const float*)d_in[p++];
    const float* fc1b = (const float*)d_in[p++];
    const float* fc2W = (const float*)d_in[p++];
    const float* fc2b = (const float*)d_in[p++];

    int N = in_sizes[0] / 128;
    int E = in_sizes[1] / 2;
    int DT = in_sizes[26];
    int G = out_size / (2 * DT + DE);
    int Mb = (N + 127) / 128;

    float *agg, *tmp, *hc;
    int *deg, *rowptr, *cursor, *gcnt, *gptr;
    cudaGetSymbolAddress((void**)&agg, g_agg);
    cudaGetSymbolAddress((void**)&tmp, g_tmp);
    cudaGetSymbolAddress((void**)&hc, g_hc);
    cudaGetSymbolAddress((void**)&deg, g_deg);
    cudaGetSymbolAddress((void**)&rowptr, g_rowptr);
    cudaGetSymbolAddress((void**)&cursor, g_cursor);
    cudaGetSymbolAddress((void**)&gcnt, g_gcnt);
    cudaGetSymbolAddress((void**)&gptr, g_gptr);

    int mx = (N > G) ? N : G;
    k_zero<<<(mx + 255) / 256, 256>>>(N, G);
    k_hist_edges<<<(E + 255) / 256, 256>>>(ei, E, N);
    k_hist_nodes<<<(N + 255) / 256, 256>>>(batch, N, G);
    int nb = (N + 255) / 256;
    k_scan_blk<<<nb, 256>>>(deg, rowptr, N);
    k_scan_top<<<1, 256>>>(nb, rowptr, cursor, N);
    k_scan_add<<<nb, 256>>>(rowptr, cursor, N);
    k_scan<<<1, 1024>>>(gcnt, gptr, gptr, G);
    k_scatter<<<(E + 255) / 256, 256>>>(ei, E, N);

    for (int l = 0; l < 4; l++) {
        const float* h = l ? (hc + (l - 1) * DE) : x;
        int ldh = l ? 1024 : 128;
        int din = l ? 256 : 128;
        k_agg<<<(N * 32 + 255) / 256, 256>>>(h, ldh, din, agg, din, N);
        dim3 gg(Mb, 2);
        // gemm1: [agg | h] @ [Wl ; Wr] + bl -> tmp
        k_gemm_mma<<<gg, 256>>>(agg, din, din, h, ldh, din,
                                Wl[l], Wr[l], bl[l], tmp, 256, N, 0);
        // gemm2: relu(tmp @ Wm + bm) -> hc[:, l*256:]
        k_gemm_mma<<<gg, 256>>>(tmp, 256, 256, nullptr, 0, 0,
                                Wm[l], nullptr, bm[l], hc + l * DE, 1024, N, 1);
    }
    k_pool<<<dim3(G, 4), 256>>>();
    k_head<<<G, 256>>>(fc1W, fc1b, fc2W, fc2b, (float*)d_out, G, DT);
}

// round 5
// speedup vs baseline: 2.0668x; 1.1051x over previous
#include <cuda_runtime.h>
#include <cuda_bf16.h>
#include <math.h>
#include <float.h>

#define DE 256
#define MAXN 50000
#define MAXG 256
#define MAXE 800000

// ------------------------------------------------------------- scratch
static __device__ int   g_deg[MAXN];
static __device__ int   g_rowptr[MAXN + 1];
static __device__ int   g_cursor[MAXN + 1];
static __device__ int   g_col[MAXE];
static __device__ int   g_gcnt[MAXG];
static __device__ int   g_gptr[MAXG + 1];
static __device__ int   g_part[512];
static __device__ float g_agg[MAXN * 256];
static __device__ float g_tmp[MAXN * 256];
static __device__ float g_hc[(size_t)MAXN * 1024];
static __device__ float g_pool[MAXG * 1024];
// pre-converted weights, packed bf16 hi/lo, layout [n=256][K]
static __device__ __align__(16) unsigned short g_W1h[4][256 * 512];
static __device__ __align__(16) unsigned short g_W1l[4][256 * 512];
static __device__ __align__(16) unsigned short g_W2h[4][256 * 256];
static __device__ __align__(16) unsigned short g_W2l[4][256 * 256];

// ---------------------------------------------------------------- utilities
__global__ void k_zero(int N, int G) {
    int i = blockIdx.x * blockDim.x + threadIdx.x;
    if (i < N) g_deg[i] = 0;
    if (i < G) g_gcnt[i] = 0;
}
__device__ __forceinline__ int clampi(int v, int n) {
    return v < 0 ? 0 : (v >= n ? n - 1 : v);
}
__global__ void k_hist_edges(const int* __restrict__ ei, int E, int N) {
    int e = blockIdx.x * blockDim.x + threadIdx.x;
    if (e < E) atomicAdd(&g_deg[clampi(ei[E + e], N)], 1);
}
__global__ void k_hist_nodes(const int* __restrict__ batch, int N, int G) {
    int i = blockIdx.x * blockDim.x + threadIdx.x;
    if (i < N) atomicAdd(&g_gcnt[clampi(batch[i], G)], 1);
}

// three-phase multi-block exclusive scan
__global__ void k_scan_blk(const int* __restrict__ in, int* __restrict__ out, int n) {
    __shared__ int ws[8], wsx[8];
    int i = blockIdx.x * 256 + threadIdx.x;
    int v = (i < n) ? in[i] : 0;
    int lane = threadIdx.x & 31, w = threadIdx.x >> 5;
    int inc = v;
#pragma unroll
    for (int o = 1; o < 32; o <<= 1) {
        int t = __shfl_up_sync(0xffffffffu, inc, o);
        if (lane >= o) inc += t;
    }
    if (lane == 31) ws[w] = inc;
    __syncthreads();
    if (threadIdx.x == 0) {
        int run = 0;
#pragma unroll
        for (int j = 0; j < 8; j++) { int t = ws[j]; wsx[j] = run; run += t; }
        g_part[blockIdx.x] = run;
    }
    __syncthreads();
    if (i < n) out[i] = inc - v + wsx[w];
}
__global__ void k_scan_top(int nb, int* outA, int* outB, int n) {
    __shared__ int ws[8], wsx[8];
    int tid = threadIdx.x;
    int v = (tid < nb) ? g_part[tid] : 0;
    int lane = tid & 31, w = tid >> 5;
    int inc = v;
#pragma unroll
    for (int o = 1; o < 32; o <<= 1) {
        int t = __shfl_up_sync(0xffffffffu, inc, o);
        if (lane >= o) inc += t;
    }
    if (lane == 31) ws[w] = inc;
    __syncthreads();
    if (tid == 0) {
        int run = 0;
#pragma unroll
        for (int j = 0; j < 8; j++) { int t = ws[j]; wsx[j] = run; run += t; }
        outA[n] = run; outB[n] = run;
    }
    __syncthreads();
    int excl = inc - v + wsx[w];
    __syncthreads();
    if (tid < nb) g_part[tid] = excl;
}
__global__ void k_scan_add(int* __restrict__ out, int* __restrict__ out2, int n) {
    int i = blockIdx.x * 256 + threadIdx.x;
    if (i < n) { int v = out[i] + g_part[blockIdx.x]; out[i] = v; out2[i] = v; }
}

__global__ void k_scan(const int* __restrict__ in, int* __restrict__ out,
                       int* __restrict__ out2, int n) {
    __shared__ int wsum[32];
    int tid = threadIdx.x;
    int chunk = (n + blockDim.x - 1) / blockDim.x;
    int s = tid * chunk, e = min(s + chunk, n);
    int local = 0;
    for (int i = s; i < e; i++) local += in[i];
    int lane = tid & 31, wid = tid >> 5;
    int v = local;
#pragma unroll
    for (int o = 1; o < 32; o <<= 1) {
        int t = __shfl_up_sync(0xffffffffu, v, o);
        if (lane >= o) v += t;
    }
    if (lane == 31) wsum[wid] = v;
    __syncthreads();
    if (wid == 0) {
        int nw = blockDim.x >> 5;
        int w = (lane < nw) ? wsum[lane] : 0;
#pragma unroll
        for (int o = 1; o < 32; o <<= 1) {
            int t = __shfl_up_sync(0xffffffffu, w, o);
            if (lane >= o) w += t;
        }
        wsum[lane] = w;
    }
    __syncthreads();
    int excl = v - local + (wid ? wsum[wid - 1] : 0);
    int run = excl;
    for (int i = s; i < e; i++) { out[i] = run; out2[i] = run; run += in[i]; }
    if (s < n && e == n) { out[n] = run; out2[n] = run; }
}

__global__ void k_scatter(const int* __restrict__ ei, int E, int N) {
    int e = blockIdx.x * blockDim.x + threadIdx.x;
    if (e < E) {
        int d = clampi(ei[E + e], N);
        int p = atomicAdd(&g_cursor[d], 1);
        if (p < MAXE) g_col[p] = clampi(ei[e], N);
    }
}

// -------------------------------------------------------------- aggregation
__device__ __forceinline__ float4 fmax4(float4 a, float4 b) {
    return make_float4(fmaxf(a.x, b.x), fmaxf(a.y, b.y),
                       fmaxf(a.z, b.z), fmaxf(a.w, b.w));
}
__global__ void k_agg(const float* __restrict__ h, int ldh, int din,
                      float* __restrict__ out, int ldo, int N) {
    int w = (blockIdx.x * blockDim.x + threadIdx.x) >> 5;
    int lane = threadIdx.x & 31;
    if (w >= N) return;
    int s = g_rowptr[w], e = g_rowptr[w + 1];
    float4 m0 = make_float4(-FLT_MAX, -FLT_MAX, -FLT_MAX, -FLT_MAX);
    float4 m1 = m0;
    if (din == 256) {
        int j = s;
        for (; j + 1 < e; j += 2) {
            const float4* r0 = (const float4*)(h + (size_t)g_col[j] * ldh);
            const float4* r1 = (const float4*)(h + (size_t)g_col[j + 1] * ldh);
            float4 a0 = r0[lane], a1 = r0[lane + 32];
            float4 b0 = r1[lane], b1 = r1[lane + 32];
            m0 = fmax4(m0, fmax4(a0, b0));
            m1 = fmax4(m1, fmax4(a1, b1));
        }
        if (j < e) {
            const float4* r = (const float4*)(h + (size_t)g_col[j] * ldh);
            m0 = fmax4(m0, r[lane]);
            m1 = fmax4(m1, r[lane + 32]);
        }
    } else {
        int j = s;
        for (; j + 1 < e; j += 2) {
            const float4* r0 = (const float4*)(h + (size_t)g_col[j] * ldh);
            const float4* r1 = (const float4*)(h + (size_t)g_col[j + 1] * ldh);
            m0 = fmax4(m0, fmax4(r0[lane], r1[lane]));
        }
        if (j < e) {
            const float4* r = (const float4*)(h + (size_t)g_col[j] * ldh);
            m0 = fmax4(m0, r[lane]);
        }
    }
    if (e == s) { m0 = make_float4(0.f, 0.f, 0.f, 0.f); m1 = m0; }
    float4* o = (float4*)(out + (size_t)w * ldo);
    o[lane] = m0;
    if (din == 256) o[lane + 32] = m1;
}

// ------------------------------------------------------ weight pre-convert
// dst layout [n=256][K]; k < K0 from W0[k][n], else W1[k-K0][n]
__device__ __forceinline__ void split_bf16(float f, unsigned short& h,
                                           unsigned short& l) {
    __nv_bfloat16 hb = __float2bfloat16(f);
    h = __bfloat16_as_ushort(hb);
    l = __bfloat16_as_ushort(__float2bfloat16(f - __bfloat162float(hb)));
}
__global__ void k_wconv(const float* __restrict__ W0, int K0,
                        const float* __restrict__ W1, int K2,
                        unsigned short* __restrict__ dh,
                        unsigned short* __restrict__ dl) {
    int K = K0 + K2;
    int idx = blockIdx.x * 256 + threadIdx.x;
    if (idx >= 256 * K) return;
    int n = idx / K, k = idx - n * K;
    float f = (k < K0) ? W0[(size_t)k * 256 + n] : W1[(size_t)(k - K0) * 256 + n];
    split_bf16(f, dh[idx], dl[idx]);
}

// ------------------------------------------------------- mma.sync bf16 GEMM
// C[M,256] = [A1 | A2] @ W + bias (optional relu), W pre-split [256][K].
// fp32 emulated via bf16 hi/lo: C = Ah*Bh + Ah*Bl + Al*Bh.
// CTA: 128(M) x 128(N), 8 warps of 64x32, K-chunk 32, ldmatrix fragments.
#define BSTR 40   // smem halves per row (32 data + 8 pad)

__device__ __forceinline__ unsigned smem_u32(const void* p) {
    unsigned a;
    asm("{ .reg .u64 t; cvta.to.shared.u64 t, %1; cvt.u32.u64 %0, t; }"
        : "=r"(a) : "l"(p));
    return a;
}
__device__ __forceinline__ void pack_hilo(float f0, float f1,
                                          unsigned& hi, unsigned& lo) {
    unsigned short h0, l0, h1, l1;
    split_bf16(f0, h0, l0);
    split_bf16(f1, h1, l1);
    hi = (unsigned)h0 | ((unsigned)h1 << 16);
    lo = (unsigned)l0 | ((unsigned)l1 << 16);
}
__device__ __forceinline__ void ldsm_x4(unsigned& r0, unsigned& r1,
                                        unsigned& r2, unsigned& r3, unsigned a) {
    asm volatile("ldmatrix.sync.aligned.m8n8.x4.shared.b16 {%0,%1,%2,%3}, [%4];"
                 : "=r"(r0), "=r"(r1), "=r"(r2), "=r"(r3) : "r"(a));
}
__device__ __forceinline__ void ldsm_x2(unsigned& r0, unsigned& r1, unsigned a) {
    asm volatile("ldmatrix.sync.aligned.m8n8.x2.shared.b16 {%0,%1}, [%2];"
                 : "=r"(r0), "=r"(r1) : "r"(a));
}
#define MMA_BF16(c, a0, a1, a2, a3, b0, b1)                                   \
    asm volatile(                                                             \
        "mma.sync.aligned.m16n8k16.row.col.f32.bf16.bf16.f32 "                \
        "{%0,%1,%2,%3}, {%4,%5,%6,%7}, {%8,%9}, {%0,%1,%2,%3};"               \
        : "+f"((c)[0]), "+f"((c)[1]), "+f"((c)[2]), "+f"((c)[3])              \
        : "r"(a0), "r"(a1), "r"(a2), "r"(a3), "r"(b0), "r"(b1))

__global__ __launch_bounds__(256, 2)
void k_gemm_mma(const float* __restrict__ A1, int lda1, int K0,
                const float* __restrict__ A2, int lda2, int K2,
                const unsigned short* __restrict__ Wh,
                const unsigned short* __restrict__ Wl_,
                const float* __restrict__ bias,
                float* __restrict__ C, int ldc, int M, int doRelu) {
    __shared__ __align__(16) unsigned short As_h[128 * BSTR];
    __shared__ __align__(16) unsigned short As_l[128 * BSTR];
    __shared__ __align__(16) unsigned short Bs_h[128 * BSTR];
    __shared__ __align__(16) unsigned short Bs_l[128 * BSTR];

    const int tid = threadIdx.x;
    const int wid = tid >> 5, lane = tid & 31;
    const int lr = lane >> 2, lc = lane & 3;
    const int m0 = blockIdx.x * 128, n0 = blockIdx.y * 128;
    const int wm = (wid >> 2) * 64, wn = (wid & 3) * 32;
    const int K = K0 + K2;
    const int nc = K >> 5;

    const unsigned baseAh = smem_u32(As_h), baseAl = smem_u32(As_l);
    const unsigned baseBh = smem_u32(Bs_h), baseBl = smem_u32(Bs_l);
    // ldmatrix per-lane offsets (halves*2 = bytes)
    const unsigned offA = ((lane & 15) * BSTR + ((lane >> 4) << 3)) * 2;
    const unsigned offB = ((lane & 7) * BSTR + (((lane >> 3) & 1) << 3)) * 2;

    float acc[4][4][4];
#pragma unroll
    for (int i = 0; i < 4; i++)
#pragma unroll
        for (int j = 0; j < 4; j++)
#pragma unroll
            for (int q = 0; q < 4; q++) acc[i][j][q] = 0.f;

    const int s_arow = tid >> 3;          // 0..31
    const int s_akq = (tid & 7) << 2;     // 0,4,..,28
    const int s_br = tid >> 1;            // 0..127
    const int s_bp = (tid & 1) << 4;      // 0 or 16 halves

    for (int t = 0; t < nc; t++) {
        int kb = t << 5;
        const float* Asel;
        int lda, kloc;
        if (kb < K0) { Asel = A1; lda = lda1; kloc = kb; }
        else         { Asel = A2; lda = lda2; kloc = kb - K0; }

        // stage A (128 x 32 fp32 -> bf16 hi/lo)
#pragma unroll
        for (int it = 0; it < 4; it++) {
            int row = s_arow + it * 32;
            int m = m0 + row;
            float4 v = make_float4(0.f, 0.f, 0.f, 0.f);
            if (m < M) v = *(const float4*)(Asel + (size_t)m * lda + kloc + s_akq);
            unsigned h0, l0, h1, l1;
            pack_hilo(v.x, v.y, h0, l0);
            pack_hilo(v.z, v.w, h1, l1);
            int idx = row * BSTR + s_akq;
            *(uint2*)&As_h[idx] = make_uint2(h0, h1);
            *(uint2*)&As_l[idx] = make_uint2(l0, l1);
        }
        // stage B: pure copies from pre-converted weights [n][K]
        {
            const uint4* sh = (const uint4*)(Wh + (size_t)(n0 + s_br) * K + kb + s_bp);
            const uint4* sl = (const uint4*)(Wl_ + (size_t)(n0 + s_br) * K + kb + s_bp);
            uint4 h0 = sh[0], h1 = sh[1];
            uint4 l0 = sl[0], l1 = sl[1];
            int idx = s_br * BSTR + s_bp;
            *(uint4*)&Bs_h[idx] = h0; *(uint4*)&Bs_h[idx + 8] = h1;
            *(uint4*)&Bs_l[idx] = l0; *(uint4*)&Bs_l[idx + 8] = l1;
        }
        __syncthreads();

#pragma unroll
        for (int ks = 0; ks < 32; ks += 16) {
            unsigned ah[4][4], al[4][4];
#pragma unroll
            for (int i = 0; i < 4; i++) {
                unsigned ad = (wm + i * 16) * BSTR * 2 + ks * 2 + offA;
                ldsm_x4(ah[i][0], ah[i][1], ah[i][2], ah[i][3], baseAh + ad);
                ldsm_x4(al[i][0], al[i][1], al[i][2], al[i][3], baseAl + ad);
            }
#pragma unroll
            for (int j = 0; j < 4; j++) {
                unsigned bd = (wn + j * 8) * BSTR * 2 + ks * 2 + offB;
                unsigned bh0, bh1, bl0, bl1;
                ldsm_x2(bh0, bh1, baseBh + bd);
                ldsm_x2(bl0, bl1, baseBl + bd);
#pragma unroll
                for (int i = 0; i < 4; i++) {
                    MMA_BF16(acc[i][j], ah[i][0], ah[i][1], ah[i][2], ah[i][3], bh0, bh1);
                    MMA_BF16(acc[i][j], ah[i][0], ah[i][1], ah[i][2], ah[i][3], bl0, bl1);
                    MMA_BF16(acc[i][j], al[i][0], al[i][1], al[i][2], al[i][3], bh0, bh1);
                }
            }
        }
        __syncthreads();
    }

    // epilogue
#pragma unroll
    for (int i = 0; i < 4; i++) {
        int row0 = m0 + wm + i * 16 + lr;
#pragma unroll
        for (int j = 0; j < 4; j++) {
            int col = n0 + wn + j * 8 + lc * 2;
            float b0 = bias[col], b1 = bias[col + 1];
            float2 v0 = make_float2(acc[i][j][0] + b0, acc[i][j][1] + b1);
            float2 v1 = make_float2(acc[i][j][2] + b0, acc[i][j][3] + b1);
            if (doRelu) {
                v0.x = fmaxf(v0.x, 0.f); v0.y = fmaxf(v0.y, 0.f);
                v1.x = fmaxf(v1.x, 0.f); v1.y = fmaxf(v1.y, 0.f);
            }
            if (row0 < M)     *(float2*)(C + (size_t)row0 * ldc + col) = v0;
            if (row0 + 8 < M) *(float2*)(C + (size_t)(row0 + 8) * ldc + col) = v1;
        }
    }
}

// -------------------------------------------------------------------- pool
__global__ void k_pool() {
    int b = blockIdx.x;
    int f = blockIdx.y * 256 + threadIdx.x;
    int s = g_gptr[b], e = g_gptr[b + 1];
    float m = -FLT_MAX;
    int n = s;
    for (; n + 3 < e; n += 4) {
        float v0 = g_hc[(size_t)(n + 0) * 1024 + f];
        float v1 = g_hc[(size_t)(n + 1) * 1024 + f];
        float v2 = g_hc[(size_t)(n + 2) * 1024 + f];
        float v3 = g_hc[(size_t)(n + 3) * 1024 + f];
        m = fmaxf(m, fmaxf(fmaxf(v0, v1), fmaxf(v2, v3)));
    }
    for (; n < e; n++) m = fmaxf(m, g_hc[(size_t)n * 1024 + f]);
    g_pool[b * 1024 + f] = (e > s) ? m : 0.f;
}

// -------------------------------------------------------------------- head
__global__ void k_head(const float* __restrict__ W1, const float* __restrict__ b1,
                       const float* __restrict__ W2, const float* __restrict__ b2,
                       float* __restrict__ outbuf, int G, int DT) {
    __shared__ float sg[1024];
    __shared__ float sl[256];
    __shared__ float so[32];
    __shared__ float slse;
    int b = blockIdx.x, t = threadIdx.x;
    for (int k = t; k < 1024; k += 256) sg[k] = g_pool[b * 1024 + k];
    __syncthreads();
    float acc = b1[t];
#pragma unroll 4
    for (int k = 0; k < 1024; k++) acc = fmaf(sg[k], W1[k * 256 + t], acc);
    acc = fmaxf(acc, 0.f);
    sl[t] = acc;
    outbuf[2 * G * DT + b * 256 + t] = acc;
    __syncthreads();
    if (t < DT) {
        float o = b2[t];
        for (int k = 0; k < 256; k++) o = fmaf(sl[k], W2[k * DT + t], o);
        so[t] = o;
    }
    __syncthreads();
    if (t == 0) {
        float mx = -FLT_MAX;
        for (int j = 0; j < DT; j++) mx = fmaxf(mx, so[j]);
        float s2 = 0.f;
        for (int j = 0; j < DT; j++) s2 += expf(so[j] - mx);
        slse = mx + logf(s2);
    }
    __syncthreads();
    if (t < DT) {
        outbuf[b * DT + t] = so[t] - slse;
        outbuf[G * DT + b * DT + t] = so[t];
    }
}

// ------------------------------------------------------------------ launch
extern "C" void kernel_launch(void* const* d_in, const int* in_sizes, int n_in,
                              void* d_out, int out_size) {
    const float* x = (const float*)d_in[0];
    const int* ei = (const int*)d_in[1];
    const int* batch = (const int*)d_in[2];
    const float *Wl[4], *bl[4], *Wr[4], *Wm[4], *bm[4];
    int p = 3;
    for (int l = 0; l < 4; l++) {
        Wl[l] = (const float*)d_in[p++];
        bl[l] = (const float*)d_in[p++];
        Wr[l] = (const float*)d_in[p++];
        Wm[l] = (const float*)d_in[p++];
        bm[l] = (const float*)d_in[p++];
    }
    const float* fc1W = (const float*)d_in[p++];
    const float* fc1b = (const float*)d_in[p++];
    const float* fc2W = (const float*)d_in[p++];
    const float* fc2b = (const float*)d_in[p++];

    int N = in_sizes[0] / 128;
    int E = in_sizes[1] / 2;
    int DT = in_sizes[26];
    int G = out_size / (2 * DT + DE);
    int Mb = (N + 127) / 128;

    float *agg, *tmp, *hc;
    int *deg, *rowptr, *cursor, *gcnt, *gptr;
    cudaGetSymbolAddress((void**)&agg, g_agg);
    cudaGetSymbolAddress((void**)&tmp, g_tmp);
    cudaGetSymbolAddress((void**)&hc, g_hc);
    cudaGetSymbolAddress((void**)&deg, g_deg);
    cudaGetSymbolAddress((void**)&rowptr, g_rowptr);
    cudaGetSymbolAddress((void**)&cursor, g_cursor);
    cudaGetSymbolAddress((void**)&gcnt, g_gcnt);
    cudaGetSymbolAddress((void**)&gptr, g_gptr);
    void *pW1h, *pW1l, *pW2h, *pW2l;
    cudaGetSymbolAddress(&pW1h, g_W1h);
    cudaGetSymbolAddress(&pW1l, g_W1l);
    cudaGetSymbolAddress(&pW2h, g_W2h);
    cudaGetSymbolAddress(&pW2l, g_W2l);

    int mx = (N > G) ? N : G;
    k_zero<<<(mx + 255) / 256, 256>>>(N, G);
    k_hist_edges<<<(E + 255) / 256, 256>>>(ei, E, N);
    k_hist_nodes<<<(N + 255) / 256, 256>>>(batch, N, G);
    int nb = (N + 255) / 256;
    k_scan_blk<<<nb, 256>>>(deg, rowptr, N);
    k_scan_top<<<1, 256>>>(nb, rowptr, cursor, N);
    k_scan_add<<<nb, 256>>>(rowptr, cursor, N);
    k_scan<<<1, 1024>>>(gcnt, gptr, gptr, G);
    k_scatter<<<(E + 255) / 256, 256>>>(ei, E, N);

    // pre-convert weights (per layer: [Wl;Wr] concat for gemm1, Wm for gemm2)
    for (int l = 0; l < 4; l++) {
        int din = l ? 256 : 128;
        int K1 = 2 * din;
        unsigned short* w1h = (unsigned short*)pW1h + (size_t)l * 256 * 512;
        unsigned short* w1l = (unsigned short*)pW1l + (size_t)l * 256 * 512;
        unsigned short* w2h = (unsigned short*)pW2h + (size_t)l * 256 * 256;
        unsigned short* w2l = (unsigned short*)pW2l + (size_t)l * 256 * 256;
        k_wconv<<<(256 * K1 + 255) / 256, 256>>>(Wl[l], din, Wr[l], din, w1h, w1l);
        k_wconv<<<(256 * 256 + 255) / 256, 256>>>(Wm[l], 256, nullptr, 0, w2h, w2l);
    }

    for (int l = 0; l < 4; l++) {
        const float* h = l ? (hc + (l - 1) * DE) : x;
        int ldh = l ? 1024 : 128;
        int din = l ? 256 : 128;
        unsigned short* w1h = (unsigned short*)pW1h + (size_t)l * 256 * 512;
        unsigned short* w1l = (unsigned short*)pW1l + (size_t)l * 256 * 512;
        unsigned short* w2h = (unsigned short*)pW2h + (size_t)l * 256 * 256;
        unsigned short* w2l = (unsigned short*)pW2l + (size_t)l * 256 * 256;
        k_agg<<<(N * 32 + 255) / 256, 256>>>(h, ldh, din, agg, din, N);
        dim3 gg(Mb, 2);
        k_gemm_mma<<<gg, 256>>>(agg, din, din, h, ldh, din,
                                w1h, w1l, bl[l], tmp, 256, N, 0);
        k_gemm_mma<<<gg, 256>>>(tmp, 256, 256, nullptr, 0, 0,
                                w2h, w2l, bm[l], hc + l * DE, 1024, N, 1);
    }
    k_pool<<<dim3(G, 4), 256>>>();
    k_head<<<G, 256>>>(fc1W, fc1b, fc2W, fc2b, (float*)d_out, G, DT);
}

// round 8
// speedup vs baseline: 2.0879x; 1.0102x over previous
#include <cuda_runtime.h>
#include <cuda_bf16.h>
#include <math.h>
#include <float.h>

#define DE 256
#define MAXN 50000
#define MAXG 256
#define MAXE 800000

// ------------------------------------------------------------- scratch
static __device__ int   g_deg[MAXN];
static __device__ int   g_rowptr[MAXN + 1];
static __device__ int   g_cursor[MAXN + 1];
static __device__ int   g_col[MAXE];
static __device__ int   g_gcnt[MAXG];
static __device__ int   g_gptr[MAXG + 1];
static __device__ int   g_part[512];
static __device__ float g_agg[MAXN * 256];
static __device__ float g_tmp[MAXN * 256];
static __device__ float g_hc[(size_t)MAXN * 1024];
static __device__ float g_pool[MAXG * 1024];
// pre-converted weights, packed bf16 hi/lo, layout [n=256][K]
static __device__ __align__(16) unsigned short g_W1h[4][256 * 512];
static __device__ __align__(16) unsigned short g_W1l[4][256 * 512];
static __device__ __align__(16) unsigned short g_W2h[4][256 * 256];
static __device__ __align__(16) unsigned short g_W2l[4][256 * 256];

// ---------------------------------------------------------------- utilities
__global__ void k_zero(int N, int G) {
    int i = blockIdx.x * blockDim.x + threadIdx.x;
    if (i < N) g_deg[i] = 0;
    if (i < G) g_gcnt[i] = 0;
}
__device__ __forceinline__ int clampi(int v, int n) {
    return v < 0 ? 0 : (v >= n ? n - 1 : v);
}
__global__ void k_hist_edges(const int* __restrict__ ei, int E, int N) {
    int e = blockIdx.x * blockDim.x + threadIdx.x;
    if (e < E) atomicAdd(&g_deg[clampi(ei[E + e], N)], 1);
}
__global__ void k_hist_nodes(const int* __restrict__ batch, int N, int G) {
    int i = blockIdx.x * blockDim.x + threadIdx.x;
    if (i < N) atomicAdd(&g_gcnt[clampi(batch[i], G)], 1);
}

// three-phase multi-block exclusive scan
__global__ void k_scan_blk(const int* __restrict__ in, int* __restrict__ out, int n) {
    __shared__ int ws[8], wsx[8];
    int i = blockIdx.x * 256 + threadIdx.x;
    int v = (i < n) ? in[i] : 0;
    int lane = threadIdx.x & 31, w = threadIdx.x >> 5;
    int inc = v;
#pragma unroll
    for (int o = 1; o < 32; o <<= 1) {
        int t = __shfl_up_sync(0xffffffffu, inc, o);
        if (lane >= o) inc += t;
    }
    if (lane == 31) ws[w] = inc;
    __syncthreads();
    if (threadIdx.x == 0) {
        int run = 0;
#pragma unroll
        for (int j = 0; j < 8; j++) { int t = ws[j]; wsx[j] = run; run += t; }
        g_part[blockIdx.x] = run;
    }
    __syncthreads();
    if (i < n) out[i] = inc - v + wsx[w];
}
__global__ void k_scan_top(int nb, int* outA, int* outB, int n) {
    __shared__ int ws[8], wsx[8];
    int tid = threadIdx.x;
    int v = (tid < nb) ? g_part[tid] : 0;
    int lane = tid & 31, w = tid >> 5;
    int inc = v;
#pragma unroll
    for (int o = 1; o < 32; o <<= 1) {
        int t = __shfl_up_sync(0xffffffffu, inc, o);
        if (lane >= o) inc += t;
    }
    if (lane == 31) ws[w] = inc;
    __syncthreads();
    if (tid == 0) {
        int run = 0;
#pragma unroll
        for (int j = 0; j < 8; j++) { int t = ws[j]; wsx[j] = run; run += t; }
        outA[n] = run; outB[n] = run;
    }
    __syncthreads();
    int excl = inc - v + wsx[w];
    __syncthreads();
    if (tid < nb) g_part[tid] = excl;
}
__global__ void k_scan_add(int* __restrict__ out, int* __restrict__ out2, int n) {
    int i = blockIdx.x * 256 + threadIdx.x;
    if (i < n) { int v = out[i] + g_part[blockIdx.x]; out[i] = v; out2[i] = v; }
}

__global__ void k_scan(const int* __restrict__ in, int* __restrict__ out,
                       int* __restrict__ out2, int n) {
    __shared__ int wsum[32];
    int tid = threadIdx.x;
    int chunk = (n + blockDim.x - 1) / blockDim.x;
    int s = tid * chunk, e = min(s + chunk, n);
    int local = 0;
    for (int i = s; i < e; i++) local += in[i];
    int lane = tid & 31, wid = tid >> 5;
    int v = local;
#pragma unroll
    for (int o = 1; o < 32; o <<= 1) {
        int t = __shfl_up_sync(0xffffffffu, v, o);
        if (lane >= o) v += t;
    }
    if (lane == 31) wsum[wid] = v;
    __syncthreads();
    if (wid == 0) {
        int nw = blockDim.x >> 5;
        int w = (lane < nw) ? wsum[lane] : 0;
#pragma unroll
        for (int o = 1; o < 32; o <<= 1) {
            int t = __shfl_up_sync(0xffffffffu, w, o);
            if (lane >= o) w += t;
        }
        wsum[lane] = w;
    }
    __syncthreads();
    int excl = v - local + (wid ? wsum[wid - 1] : 0);
    int run = excl;
    for (int i = s; i < e; i++) { out[i] = run; out2[i] = run; run += in[i]; }
    if (s < n && e == n) { out[n] = run; out2[n] = run; }
}

__global__ void k_scatter(const int* __restrict__ ei, int E, int N) {
    int e = blockIdx.x * blockDim.x + threadIdx.x;
    if (e < E) {
        int d = clampi(ei[E + e], N);
        int p = atomicAdd(&g_cursor[d], 1);
        if (p < MAXE) g_col[p] = clampi(ei[e], N);
    }
}

// -------------------------------------------------------------- aggregation
__device__ __forceinline__ float4 fmax4(float4 a, float4 b) {
    return make_float4(fmaxf(a.x, b.x), fmaxf(a.y, b.y),
                       fmaxf(a.z, b.z), fmaxf(a.w, b.w));
}
__global__ void k_agg(const float* __restrict__ h, int ldh, int din,
                      float* __restrict__ out, int ldo, int N) {
    int w = (blockIdx.x * blockDim.x + threadIdx.x) >> 5;
    int lane = threadIdx.x & 31;
    if (w >= N) return;
    int s = g_rowptr[w], e = g_rowptr[w + 1];
    float4 m0 = make_float4(-FLT_MAX, -FLT_MAX, -FLT_MAX, -FLT_MAX);
    float4 m1 = m0;
    if (din == 256) {
        int j = s;
        for (; j + 1 < e; j += 2) {
            const float4* r0 = (const float4*)(h + (size_t)g_col[j] * ldh);
            const float4* r1 = (const float4*)(h + (size_t)g_col[j + 1] * ldh);
            float4 a0 = r0[lane], a1 = r0[lane + 32];
            float4 b0 = r1[lane], b1 = r1[lane + 32];
            m0 = fmax4(m0, fmax4(a0, b0));
            m1 = fmax4(m1, fmax4(a1, b1));
        }
        if (j < e) {
            const float4* r = (const float4*)(h + (size_t)g_col[j] * ldh);
            m0 = fmax4(m0, r[lane]);
            m1 = fmax4(m1, r[lane + 32]);
        }
    } else {
        int j = s;
        for (; j + 1 < e; j += 2) {
            const float4* r0 = (const float4*)(h + (size_t)g_col[j] * ldh);
            const float4* r1 = (const float4*)(h + (size_t)g_col[j + 1] * ldh);
            m0 = fmax4(m0, fmax4(r0[lane], r1[lane]));
        }
        if (j < e) {
            const float4* r = (const float4*)(h + (size_t)g_col[j] * ldh);
            m0 = fmax4(m0, r[lane]);
        }
    }
    if (e == s) { m0 = make_float4(0.f, 0.f, 0.f, 0.f); m1 = m0; }
    float4* o = (float4*)(out + (size_t)w * ldo);
    o[lane] = m0;
    if (din == 256) o[lane + 32] = m1;
}

// ------------------------------------------------------ weight pre-convert
__device__ __forceinline__ void split_bf16(float f, unsigned short& h,
                                           unsigned short& l) {
    __nv_bfloat16 hb = __float2bfloat16(f);
    h = __bfloat16_as_ushort(hb);
    l = __bfloat16_as_ushort(__float2bfloat16(f - __bfloat162float(hb)));
}
__global__ void k_wconv(const float* __restrict__ W0, int K0,
                        const float* __restrict__ W1, int K2,
                        unsigned short* __restrict__ dh,
                        unsigned short* __restrict__ dl) {
    int K = K0 + K2;
    int idx = blockIdx.x * 256 + threadIdx.x;
    if (idx >= 256 * K) return;
    int n = idx / K, k = idx - n * K;
    float f = (k < K0) ? W0[(size_t)k * 256 + n] : W1[(size_t)(k - K0) * 256 + n];
    split_bf16(f, dh[idx], dl[idx]);
}

// ------------------------------------------------------- mma.sync bf16 GEMM
// C[M,256] = [A1 | A2] @ W + bias (optional relu), W pre-split [256][K].
// fp32 emulated via bf16 hi/lo: C = Ah*Bh + Ah*Bl + Al*Bh.
// CTA 128x128, 8 warps 64x32, K-chunk 32, ldmatrix, DOUBLE-BUFFERED smem,
// cp.async for B, register-prefetch for A.
#define BSTR 40                 // smem halves per row (32 data + 8 pad)
#define STG_H (128 * BSTR)      // halves per array (5120)
#define STG_B (4 * STG_H * 2)   // bytes per stage (40960)
#define GEMM_SMEM (2 * STG_B)   // 81920

__device__ __forceinline__ unsigned smem_u32(const void* p) {
    unsigned a;
    asm("{ .reg .u64 t; cvta.to.shared.u64 t, %1; cvt.u32.u64 %0, t; }"
        : "=r"(a) : "l"(p));
    return a;
}
__device__ __forceinline__ void pack_hilo(float f0, float f1,
                                          unsigned& hi, unsigned& lo) {
    unsigned short h0, l0, h1, l1;
    split_bf16(f0, h0, l0);
    split_bf16(f1, h1, l1);
    hi = (unsigned)h0 | ((unsigned)h1 << 16);
    lo = (unsigned)l0 | ((unsigned)l1 << 16);
}
__device__ __forceinline__ void ldsm_x4(unsigned& r0, unsigned& r1,
                                        unsigned& r2, unsigned& r3, unsigned a) {
    asm volatile("ldmatrix.sync.aligned.m8n8.x4.shared.b16 {%0,%1,%2,%3}, [%4];"
                 : "=r"(r0), "=r"(r1), "=r"(r2), "=r"(r3) : "r"(a));
}
__device__ __forceinline__ void ldsm_x2(unsigned& r0, unsigned& r1, unsigned a) {
    asm volatile("ldmatrix.sync.aligned.m8n8.x2.shared.b16 {%0,%1}, [%2];"
                 : "=r"(r0), "=r"(r1) : "r"(a));
}
__device__ __forceinline__ void cp16(unsigned dst, const void* src) {
    asm volatile("cp.async.cg.shared.global [%0], [%1], 16;"
                 :: "r"(dst), "l"(src));
}
#define MMA_BF16(c, a0, a1, a2, a3, b0, b1)                                   \
    asm volatile(                                                             \
        "mma.sync.aligned.m16n8k16.row.col.f32.bf16.bf16.f32 "                \
        "{%0,%1,%2,%3}, {%4,%5,%6,%7}, {%8,%9}, {%0,%1,%2,%3};"               \
        : "+f"((c)[0]), "+f"((c)[1]), "+f"((c)[2]), "+f"((c)[3])              \
        : "r"(a0), "r"(a1), "r"(a2), "r"(a3), "r"(b0), "r"(b1))

__global__ __launch_bounds__(256, 2)
void k_gemm_mma(const float* __restrict__ A1, int lda1, int K0,
                const float* __restrict__ A2, int lda2, int K2,
                const unsigned short* __restrict__ Wh,
                const unsigned short* __restrict__ Wl_,
                const float* __restrict__ bias,
                float* __restrict__ C, int ldc, int M, int doRelu) {
    extern __shared__ __align__(16) unsigned short sm[];

    const int tid = threadIdx.x;
    const int wid = tid >> 5, lane = tid & 31;
    const int lr = lane >> 2, lc = lane & 3;
    const int m0 = blockIdx.x * 128, n0 = blockIdx.y * 128;
    const int wm = (wid >> 2) * 64, wn = (wid & 3) * 32;
    const int K = K0 + K2;
    const int nc = K >> 5;

    const unsigned sbase = smem_u32(sm);
    const unsigned offA = ((lane & 15) * BSTR + ((lane >> 4) << 3)) * 2;
    const unsigned offB = ((lane & 7) * BSTR + (((lane >> 3) & 1) << 3)) * 2;

    float acc[4][4][4];
#pragma unroll
    for (int i = 0; i < 4; i++)
#pragma unroll
        for (int j = 0; j < 4; j++)
#pragma unroll
            for (int q = 0; q < 4; q++) acc[i][j][q] = 0.f;

    const int s_arow = tid >> 3;          // 0..31
    const int s_akq = (tid & 7) << 2;     // 0,4,..,28
    const int s_br = tid >> 1;            // 0..127
    const int s_bp = (tid & 1) << 4;      // 0 or 16 halves

    float4 av[4];

    auto loadA = [&](int t) {
        int kb = t << 5;
        const float* Asel;
        int lda, kloc;
        if (kb < K0) { Asel = A1; lda = lda1; kloc = kb; }
        else         { Asel = A2; lda = lda2; kloc = kb - K0; }
#pragma unroll
        for (int it = 0; it < 4; it++) {
            int m = m0 + s_arow + it * 32;
            av[it] = (m < M)
                ? *(const float4*)(Asel + (size_t)m * lda + kloc + s_akq)
                : make_float4(0.f, 0.f, 0.f, 0.f);
        }
    };
    auto storeA = [&](int buf) {
        unsigned short* Ah = sm + buf * (4 * STG_H);
        unsigned short* Al = Ah + STG_H;
#pragma unroll
        for (int it = 0; it < 4; it++) {
            unsigned h0, l0, h1, l1;
            pack_hilo(av[it].x, av[it].y, h0, l0);
            pack_hilo(av[it].z, av[it].w, h1, l1);
            int idx = (s_arow + it * 32) * BSTR + s_akq;
            *(uint2*)&Ah[idx] = make_uint2(h0, h1);
            *(uint2*)&Al[idx] = make_uint2(l0, l1);
        }
    };
    auto loadB = [&](int t, int buf) {
        int kb = t << 5;
        unsigned bh = sbase + buf * STG_B + 2u * (2 * STG_H) +
                      (s_br * BSTR + s_bp) * 2;
        unsigned bl = bh + STG_H * 2;
        const unsigned short* srch = Wh + (size_t)(n0 + s_br) * K + kb + s_bp;
        const unsigned short* srcl = Wl_ + (size_t)(n0 + s_br) * K + kb + s_bp;
        cp16(bh, srch);       cp16(bh + 16, srch + 8);
        cp16(bl, srcl);       cp16(bl + 16, srcl + 8);
        asm volatile("cp.async.commit_group;");
    };
    auto compute = [&](int buf) {
        unsigned baseAh = sbase + buf * STG_B;
        unsigned baseAl = baseAh + STG_H * 2;
        unsigned baseBh = baseAl + STG_H * 2;
        unsigned baseBl = baseBh + STG_H * 2;
#pragma unroll
        for (int ks = 0; ks < 32; ks += 16) {
            unsigned ah[4][4], al[4][4];
#pragma unroll
            for (int i = 0; i < 4; i++) {
                unsigned ad = (wm + i * 16) * BSTR * 2 + ks * 2 + offA;
                ldsm_x4(ah[i][0], ah[i][1], ah[i][2], ah[i][3], baseAh + ad);
                ldsm_x4(al[i][0], al[i][1], al[i][2], al[i][3], baseAl + ad);
            }
#pragma unroll
            for (int j = 0; j < 4; j++) {
                unsigned bd = (wn + j * 8) * BSTR * 2 + ks * 2 + offB;
                unsigned bh0, bh1, bl0, bl1;
                ldsm_x2(bh0, bh1, baseBh + bd);
                ldsm_x2(bl0, bl1, baseBl + bd);
#pragma unroll
                for (int i = 0; i < 4; i++) {
                    MMA_BF16(acc[i][j], ah[i][0], ah[i][1], ah[i][2], ah[i][3], bh0, bh1);
                    MMA_BF16(acc[i][j], ah[i][0], ah[i][1], ah[i][2], ah[i][3], bl0, bl1);
                    MMA_BF16(acc[i][j], al[i][0], al[i][1], al[i][2], al[i][3], bh0, bh1);
                }
            }
        }
    };

    // prologue: stage 0
    loadA(0);
    loadB(0, 0);
    storeA(0);
    asm volatile("cp.async.wait_group 0;");
    __syncthreads();

    for (int t = 0; t < nc; t++) {
        int buf = t & 1;
        bool more = (t + 1 < nc);
        if (more) { loadA(t + 1); loadB(t + 1, buf ^ 1); }
        compute(buf);
        if (more) {
            storeA(buf ^ 1);
            asm volatile("cp.async.wait_group 0;");
        }
        __syncthreads();
    }

    // epilogue
#pragma unroll
    for (int i = 0; i < 4; i++) {
        int row0 = m0 + wm + i * 16 + lr;
#pragma unroll
        for (int j = 0; j < 4; j++) {
            int col = n0 + wn + j * 8 + lc * 2;
            float b0 = bias[col], b1 = bias[col + 1];
            float2 v0 = make_float2(acc[i][j][0] + b0, acc[i][j][1] + b1);
            float2 v1 = make_float2(acc[i][j][2] + b0, acc[i][j][3] + b1);
            if (doRelu) {
                v0.x = fmaxf(v0.x, 0.f); v0.y = fmaxf(v0.y, 0.f);
                v1.x = fmaxf(v1.x, 0.f); v1.y = fmaxf(v1.y, 0.f);
            }
            if (row0 < M)     *(float2*)(C + (size_t)row0 * ldc + col) = v0;
            if (row0 + 8 < M) *(float2*)(C + (size_t)(row0 + 8) * ldc + col) = v1;
        }
    }
}

// -------------------------------------------------------------------- pool
__global__ void k_pool() {
    int b = blockIdx.x;
    int f = blockIdx.y * 256 + threadIdx.x;
    int s = g_gptr[b], e = g_gptr[b + 1];
    float m = -FLT_MAX;
    int n = s;
    for (; n + 3 < e; n += 4) {
        float v0 = g_hc[(size_t)(n + 0) * 1024 + f];
        float v1 = g_hc[(size_t)(n + 1) * 1024 + f];
        float v2 = g_hc[(size_t)(n + 2) * 1024 + f];
        float v3 = g_hc[(size_t)(n + 3) * 1024 + f];
        m = fmaxf(m, fmaxf(fmaxf(v0, v1), fmaxf(v2, v3)));
    }
    for (; n < e; n++) m = fmaxf(m, g_hc[(size_t)n * 1024 + f]);
    g_pool[b * 1024 + f] = (e > s) ? m : 0.f;
}

// -------------------------------------------------------------------- head
__global__ void k_head(const float* __restrict__ W1, const float* __restrict__ b1,
                       const float* __restrict__ W2, const float* __restrict__ b2,
                       float* __restrict__ outbuf, int G, int DT) {
    __shared__ float sg[1024];
    __shared__ float sl[256];
    __shared__ float so[32];
    __shared__ float slse;
    int b = blockIdx.x, t = threadIdx.x;
    for (int k = t; k < 1024; k += 256) sg[k] = g_pool[b * 1024 + k];
    __syncthreads();
    float acc = b1[t];
#pragma unroll 4
    for (int k = 0; k < 1024; k++) acc = fmaf(sg[k], W1[k * 256 + t], acc);
    acc = fmaxf(acc, 0.f);
    sl[t] = acc;
    outbuf[2 * G * DT + b * 256 + t] = acc;
    __syncthreads();
    if (t < DT) {
        float o = b2[t];
        for (int k = 0; k < 256; k++) o = fmaf(sl[k], W2[k * DT + t], o);
        so[t] = o;
    }
    __syncthreads();
    if (t == 0) {
        float mx = -FLT_MAX;
        for (int j = 0; j < DT; j++) mx = fmaxf(mx, so[j]);
        float s2 = 0.f;
        for (int j = 0; j < DT; j++) s2 += expf(so[j] - mx);
        slse = mx + logf(s2);
    }
    __syncthreads();
    if (t < DT) {
        outbuf[b * DT + t] = so[t] - slse;
        outbuf[G * DT + b * DT + t] = so[t];
    }
}

// ------------------------------------------------------------------ launch
extern "C" void kernel_launch(void* const* d_in, const int* in_sizes, int n_in,
                              void* d_out, int out_size) {
    const float* x = (const float*)d_in[0];
    const int* ei = (const int*)d_in[1];
    const int* batch = (const int*)d_in[2];
    const float *Wl[4], *bl[4], *Wr[4], *Wm[4], *bm[4];
    int p = 3;
    for (int l = 0; l < 4; l++) {
        Wl[l] = (const float*)d_in[p++];
        bl[l] = (const float*)d_in[p++];
        Wr[l] = (const float*)d_in[p++];
        Wm[l] = (const float*)d_in[p++];
        bm[l] = (const float*)d_in[p++];
    }
    const float* fc1W = (const float*)d_in[p++];
    const float* fc1b = (const float*)d_in[p++];
    const float* fc2W = (const float*)d_in[p++];
    const float* fc2b = (const float*)d_in[p++];

    int N = in_sizes[0] / 128;
    int E = in_sizes[1] / 2;
    int DT = in_sizes[26];
    int G = out_size / (2 * DT + DE);
    int Mb = (N + 127) / 128;

    float *agg, *tmp, *hc;
    int *deg, *rowptr, *cursor, *gcnt, *gptr;
    cudaGetSymbolAddress((void**)&agg, g_agg);
    cudaGetSymbolAddress((void**)&tmp, g_tmp);
    cudaGetSymbolAddress((void**)&hc, g_hc);
    cudaGetSymbolAddress((void**)&deg, g_deg);
    cudaGetSymbolAddress((void**)&rowptr, g_rowptr);
    cudaGetSymbolAddress((void**)&cursor, g_cursor);
    cudaGetSymbolAddress((void**)&gcnt, g_gcnt);
    cudaGetSymbolAddress((void**)&gptr, g_gptr);
    void *pW1h, *pW1l, *pW2h, *pW2l;
    cudaGetSymbolAddress(&pW1h, g_W1h);
    cudaGetSymbolAddress(&pW1l, g_W1l);
    cudaGetSymbolAddress(&pW2h, g_W2h);
    cudaGetSymbolAddress(&pW2l, g_W2l);

    cudaFuncSetAttribute(k_gemm_mma,
                         cudaFuncAttributeMaxDynamicSharedMemorySize, GEMM_SMEM);

    int mx = (N > G) ? N : G;
    k_zero<<<(mx + 255) / 256, 256>>>(N, G);
    k_hist_edges<<<(E + 255) / 256, 256>>>(ei, E, N);
    k_hist_nodes<<<(N + 255) / 256, 256>>>(batch, N, G);
    int nb = (N + 255) / 256;
    k_scan_blk<<<nb, 256>>>(deg, rowptr, N);
    k_scan_top<<<1, 256>>>(nb, rowptr, cursor, N);
    k_scan_add<<<nb, 256>>>(rowptr, cursor, N);
    k_scan<<<1, 1024>>>(gcnt, gptr, gptr, G);
    k_scatter<<<(E + 255) / 256, 256>>>(ei, E, N);

    for (int l = 0; l < 4; l++) {
        int din = l ? 256 : 128;
        int K1 = 2 * din;
        unsigned short* w1h = (unsigned short*)pW1h + (size_t)l * 256 * 512;
        unsigned short* w1l = (unsigned short*)pW1l + (size_t)l * 256 * 512;
        unsigned short* w2h = (unsigned short*)pW2h + (size_t)l * 256 * 256;
        unsigned short* w2l = (unsigned short*)pW2l + (size_t)l * 256 * 256;
        k_wconv<<<(256 * K1 + 255) / 256, 256>>>(Wl[l], din, Wr[l], din, w1h, w1l);
        k_wconv<<<(256 * 256 + 255) / 256, 256>>>(Wm[l], 256, nullptr, 0, w2h, w2l);
    }

    for (int l = 0; l < 4; l++) {
        const float* h = l ? (hc + (l - 1) * DE) : x;
        int ldh = l ? 1024 : 128;
        int din = l ? 256 : 128;
        unsigned short* w1h = (unsigned short*)pW1h + (size_t)l * 256 * 512;
        unsigned short* w1l = (unsigned short*)pW1l + (size_t)l * 256 * 512;
        unsigned short* w2h = (unsigned short*)pW2h + (size_t)l * 256 * 256;
        unsigned short* w2l = (unsigned short*)pW2l + (size_t)l * 256 * 256;
        k_agg<<<(N * 32 + 255) / 256, 256>>>(h, ldh, din, agg, din, N);
        dim3 gg(Mb, 2);
        k_gemm_mma<<<gg, 256, GEMM_SMEM>>>(agg, din, din, h, ldh, din,
                                           w1h, w1l, bl[l], tmp, 256, N, 0);
        k_gemm_mma<<<gg, 256, GEMM_SMEM>>>(tmp, 256, 256, nullptr, 0, 0,
                                           w2h, w2l, bm[l], hc + l * DE, 1024, N, 1);
    }
    k_pool<<<dim3(G, 4), 256>>>();
    k_head<<<G, 256>>>(fc1W, fc1b, fc2W, fc2b, (float*)d_out, G, DT);
}

// round 9
// speedup vs baseline: 2.6222x; 1.2559x over previous
#include <cuda_runtime.h>
#include <cuda_fp16.h>
#include <math.h>
#include <float.h>

#define DE 256
#define MAXN 50000
#define MAXG 256
#define MAXE 800000

// ------------------------------------------------------------- scratch
static __device__ int   g_deg[MAXN];
static __device__ int   g_rowptr[MAXN + 1];
static __device__ int   g_cursor[MAXN + 1];
static __device__ int   g_col[MAXE];
static __device__ int   g_gcnt[MAXG];
static __device__ int   g_gptr[MAXG + 1];
static __device__ int   g_part[512];
static __device__ float g_agg[MAXN * 256];
static __device__ float g_tmp[MAXN * 256];
static __device__ float g_hc[(size_t)MAXN * 1024];
static __device__ float g_pool[MAXG * 1024];
// pre-converted weights, fp16 (round-to-nearest), layout [n=256][K]
static __device__ __align__(16) unsigned short g_W1h[4][256 * 512];
static __device__ __align__(16) unsigned short g_W2h[4][256 * 256];

// ---------------------------------------------------------------- utilities
__global__ void k_zero(int N, int G) {
    int i = blockIdx.x * blockDim.x + threadIdx.x;
    if (i < N) g_deg[i] = 0;
    if (i < G) g_gcnt[i] = 0;
}
__device__ __forceinline__ int clampi(int v, int n) {
    return v < 0 ? 0 : (v >= n ? n - 1 : v);
}
__global__ void k_hist_edges(const int* __restrict__ ei, int E, int N) {
    int e = blockIdx.x * blockDim.x + threadIdx.x;
    if (e < E) atomicAdd(&g_deg[clampi(ei[E + e], N)], 1);
}
__global__ void k_hist_nodes(const int* __restrict__ batch, int N, int G) {
    int i = blockIdx.x * blockDim.x + threadIdx.x;
    if (i < N) atomicAdd(&g_gcnt[clampi(batch[i], G)], 1);
}

// three-phase multi-block exclusive scan
__global__ void k_scan_blk(const int* __restrict__ in, int* __restrict__ out, int n) {
    __shared__ int ws[8], wsx[8];
    int i = blockIdx.x * 256 + threadIdx.x;
    int v = (i < n) ? in[i] : 0;
    int lane = threadIdx.x & 31, w = threadIdx.x >> 5;
    int inc = v;
#pragma unroll
    for (int o = 1; o < 32; o <<= 1) {
        int t = __shfl_up_sync(0xffffffffu, inc, o);
        if (lane >= o) inc += t;
    }
    if (lane == 31) ws[w] = inc;
    __syncthreads();
    if (threadIdx.x == 0) {
        int run = 0;
#pragma unroll
        for (int j = 0; j < 8; j++) { int t = ws[j]; wsx[j] = run; run += t; }
        g_part[blockIdx.x] = run;
    }
    __syncthreads();
    if (i < n) out[i] = inc - v + wsx[w];
}
__global__ void k_scan_top(int nb, int* outA, int* outB, int n) {
    __shared__ int ws[8], wsx[8];
    int tid = threadIdx.x;
    int v = (tid < nb) ? g_part[tid] : 0;
    int lane = tid & 31, w = tid >> 5;
    int inc = v;
#pragma unroll
    for (int o = 1; o < 32; o <<= 1) {
        int t = __shfl_up_sync(0xffffffffu, inc, o);
        if (lane >= o) inc += t;
    }
    if (lane == 31) ws[w] = inc;
    __syncthreads();
    if (tid == 0) {
        int run = 0;
#pragma unroll
        for (int j = 0; j < 8; j++) { int t = ws[j]; wsx[j] = run; run += t; }
        outA[n] = run; outB[n] = run;
    }
    __syncthreads();
    int excl = inc - v + wsx[w];
    __syncthreads();
    if (tid < nb) g_part[tid] = excl;
}
__global__ void k_scan_add(int* __restrict__ out, int* __restrict__ out2, int n) {
    int i = blockIdx.x * 256 + threadIdx.x;
    if (i < n) { int v = out[i] + g_part[blockIdx.x]; out[i] = v; out2[i] = v; }
}

__global__ void k_scan(const int* __restrict__ in, int* __restrict__ out,
                       int* __restrict__ out2, int n) {
    __shared__ int wsum[32];
    int tid = threadIdx.x;
    int chunk = (n + blockDim.x - 1) / blockDim.x;
    int s = tid * chunk, e = min(s + chunk, n);
    int local = 0;
    for (int i = s; i < e; i++) local += in[i];
    int lane = tid & 31, wid = tid >> 5;
    int v = local;
#pragma unroll
    for (int o = 1; o < 32; o <<= 1) {
        int t = __shfl_up_sync(0xffffffffu, v, o);
        if (lane >= o) v += t;
    }
    if (lane == 31) wsum[wid] = v;
    __syncthreads();
    if (wid == 0) {
        int nw = blockDim.x >> 5;
        int w = (lane < nw) ? wsum[lane] : 0;
#pragma unroll
        for (int o = 1; o < 32; o <<= 1) {
            int t = __shfl_up_sync(0xffffffffu, w, o);
            if (lane >= o) w += t;
        }
        wsum[lane] = w;
    }
    __syncthreads();
    int excl = v - local + (wid ? wsum[wid - 1] : 0);
    int run = excl;
    for (int i = s; i < e; i++) { out[i] = run; out2[i] = run; run += in[i]; }
    if (s < n && e == n) { out[n] = run; out2[n] = run; }
}

__global__ void k_scatter(const int* __restrict__ ei, int E, int N) {
    int e = blockIdx.x * blockDim.x + threadIdx.x;
    if (e < E) {
        int d = clampi(ei[E + e], N);
        int p = atomicAdd(&g_cursor[d], 1);
        if (p < MAXE) g_col[p] = clampi(ei[e], N);
    }
}

// -------------------------------------------------------------- aggregation
__device__ __forceinline__ float4 fmax4(float4 a, float4 b) {
    return make_float4(fmaxf(a.x, b.x), fmaxf(a.y, b.y),
                       fmaxf(a.z, b.z), fmaxf(a.w, b.w));
}
__global__ void k_agg(const float* __restrict__ h, int ldh, int din,
                      float* __restrict__ out, int ldo, int N) {
    int w = (blockIdx.x * blockDim.x + threadIdx.x) >> 5;
    int lane = threadIdx.x & 31;
    if (w >= N) return;
    int s = g_rowptr[w], e = g_rowptr[w + 1];
    float4 m0 = make_float4(-FLT_MAX, -FLT_MAX, -FLT_MAX, -FLT_MAX);
    float4 m1 = m0;
    if (din == 256) {
        int j = s;
        for (; j + 1 < e; j += 2) {
            const float4* r0 = (const float4*)(h + (size_t)g_col[j] * ldh);
            const float4* r1 = (const float4*)(h + (size_t)g_col[j + 1] * ldh);
            float4 a0 = r0[lane], a1 = r0[lane + 32];
            float4 b0 = r1[lane], b1 = r1[lane + 32];
            m0 = fmax4(m0, fmax4(a0, b0));
            m1 = fmax4(m1, fmax4(a1, b1));
        }
        if (j < e) {
            const float4* r = (const float4*)(h + (size_t)g_col[j] * ldh);
            m0 = fmax4(m0, r[lane]);
            m1 = fmax4(m1, r[lane + 32]);
        }
    } else {
        int j = s;
        for (; j + 1 < e; j += 2) {
            const float4* r0 = (const float4*)(h + (size_t)g_col[j] * ldh);
            const float4* r1 = (const float4*)(h + (size_t)g_col[j + 1] * ldh);
            m0 = fmax4(m0, fmax4(r0[lane], r1[lane]));
        }
        if (j < e) {
            const float4* r = (const float4*)(h + (size_t)g_col[j] * ldh);
            m0 = fmax4(m0, r[lane]);
        }
    }
    if (e == s) { m0 = make_float4(0.f, 0.f, 0.f, 0.f); m1 = m0; }
    float4* o = (float4*)(out + (size_t)w * ldo);
    o[lane] = m0;
    if (din == 256) o[lane + 32] = m1;
}

// ------------------------------------------------------ weight pre-convert
// dst layout [n=256][K] fp16; k < K0 from W0[k][n], else W1[k-K0][n]
__global__ void k_wconv(const float* __restrict__ W0, int K0,
                        const float* __restrict__ W1, int K2,
                        unsigned short* __restrict__ dh) {
    int K = K0 + K2;
    int idx = blockIdx.x * 256 + threadIdx.x;
    if (idx >= 256 * K) return;
    int n = idx / K, k = idx - n * K;
    float f = (k < K0) ? W0[(size_t)k * 256 + n] : W1[(size_t)(k - K0) * 256 + n];
    dh[idx] = __half_as_ushort(__float2half_rn(f));
}

// ------------------------------------------------------- mma.sync fp16 GEMM
// C[M,256] = [A1 | A2] @ W + bias (optional relu), W pre-rounded fp16 [256][K].
// fp32 A emulated via fp16 hi/lo split: C = Ah*Bh + Al*Bh  (= A * fp16(B)).
// CTA 128x128, 8 warps 64x32, K-chunk 32, ldmatrix, double-buffered smem,
// cp.async for B, register-prefetch for A.
#define BSTR 40                 // smem halves per row (32 data + 8 pad)
#define STG_H (128 * BSTR)      // halves per array (5120)
#define STG_B (3 * STG_H * 2)   // bytes per stage: Ah, Al, Bh (30720)
#define GEMM_SMEM (2 * STG_B)   // 61440

__device__ __forceinline__ unsigned smem_u32(const void* p) {
    unsigned a;
    asm("{ .reg .u64 t; cvta.to.shared.u64 t, %1; cvt.u32.u64 %0, t; }"
        : "=r"(a) : "l"(p));
    return a;
}
__device__ __forceinline__ void split_f16(float f, unsigned short& h,
                                          unsigned short& l) {
    __half hb = __float2half_rn(f);
    h = __half_as_ushort(hb);
    l = __half_as_ushort(__float2half_rn(f - __half2float(hb)));
}
__device__ __forceinline__ void pack_hilo(float f0, float f1,
                                          unsigned& hi, unsigned& lo) {
    unsigned short h0, l0, h1, l1;
    split_f16(f0, h0, l0);
    split_f16(f1, h1, l1);
    hi = (unsigned)h0 | ((unsigned)h1 << 16);
    lo = (unsigned)l0 | ((unsigned)l1 << 16);
}
__device__ __forceinline__ void ldsm_x4(unsigned& r0, unsigned& r1,
                                        unsigned& r2, unsigned& r3, unsigned a) {
    asm volatile("ldmatrix.sync.aligned.m8n8.x4.shared.b16 {%0,%1,%2,%3}, [%4];"
                 : "=r"(r0), "=r"(r1), "=r"(r2), "=r"(r3) : "r"(a));
}
__device__ __forceinline__ void ldsm_x2(unsigned& r0, unsigned& r1, unsigned a) {
    asm volatile("ldmatrix.sync.aligned.m8n8.x2.shared.b16 {%0,%1}, [%2];"
                 : "=r"(r0), "=r"(r1) : "r"(a));
}
__device__ __forceinline__ void cp16(unsigned dst, const void* src) {
    asm volatile("cp.async.cg.shared.global [%0], [%1], 16;"
                 :: "r"(dst), "l"(src));
}
#define MMA_F16(c, a0, a1, a2, a3, b0, b1)                                    \
    asm volatile(                                                             \
        "mma.sync.aligned.m16n8k16.row.col.f32.f16.f16.f32 "                  \
        "{%0,%1,%2,%3}, {%4,%5,%6,%7}, {%8,%9}, {%0,%1,%2,%3};"               \
        : "+f"((c)[0]), "+f"((c)[1]), "+f"((c)[2]), "+f"((c)[3])              \
        : "r"(a0), "r"(a1), "r"(a2), "r"(a3), "r"(b0), "r"(b1))

__global__ __launch_bounds__(256, 2)
void k_gemm_mma(const float* __restrict__ A1, int lda1, int K0,
                const float* __restrict__ A2, int lda2, int K2,
                const unsigned short* __restrict__ Wh,
                const float* __restrict__ bias,
                float* __restrict__ C, int ldc, int M, int doRelu) {
    extern __shared__ __align__(16) unsigned short sm[];

    const int tid = threadIdx.x;
    const int wid = tid >> 5, lane = tid & 31;
    const int lr = lane >> 2, lc = lane & 3;
    const int m0 = blockIdx.x * 128, n0 = blockIdx.y * 128;
    const int wm = (wid >> 2) * 64, wn = (wid & 3) * 32;
    const int K = K0 + K2;
    const int nc = K >> 5;

    const unsigned sbase = smem_u32(sm);
    const unsigned offA = ((lane & 15) * BSTR + ((lane >> 4) << 3)) * 2;
    const unsigned offB = ((lane & 7) * BSTR + (((lane >> 3) & 1) << 3)) * 2;

    float acc[4][4][4];
#pragma unroll
    for (int i = 0; i < 4; i++)
#pragma unroll
        for (int j = 0; j < 4; j++)
#pragma unroll
            for (int q = 0; q < 4; q++) acc[i][j][q] = 0.f;

    const int s_arow = tid >> 3;          // 0..31
    const int s_akq = (tid & 7) << 2;     // 0,4,..,28
    const int s_br = tid >> 1;            // 0..127
    const int s_bp = (tid & 1) << 4;      // 0 or 16 halves

    float4 av[4];

    auto loadA = [&](int t) {
        int kb = t << 5;
        const float* Asel;
        int lda, kloc;
        if (kb < K0) { Asel = A1; lda = lda1; kloc = kb; }
        else         { Asel = A2; lda = lda2; kloc = kb - K0; }
#pragma unroll
        for (int it = 0; it < 4; it++) {
            int m = m0 + s_arow + it * 32;
            av[it] = (m < M)
                ? *(const float4*)(Asel + (size_t)m * lda + kloc + s_akq)
                : make_float4(0.f, 0.f, 0.f, 0.f);
        }
    };
    auto storeA = [&](int buf) {
        unsigned short* Ah = sm + buf * (3 * STG_H);
        unsigned short* Al = Ah + STG_H;
#pragma unroll
        for (int it = 0; it < 4; it++) {
            unsigned h0, l0, h1, l1;
            pack_hilo(av[it].x, av[it].y, h0, l0);
            pack_hilo(av[it].z, av[it].w, h1, l1);
            int idx = (s_arow + it * 32) * BSTR + s_akq;
            *(uint2*)&Ah[idx] = make_uint2(h0, h1);
            *(uint2*)&Al[idx] = make_uint2(l0, l1);
        }
    };
    auto loadB = [&](int t, int buf) {
        int kb = t << 5;
        unsigned bh = sbase + buf * STG_B + 4u * STG_H +
                      (s_br * BSTR + s_bp) * 2;
        const unsigned short* srch = Wh + (size_t)(n0 + s_br) * K + kb + s_bp;
        cp16(bh, srch);
        cp16(bh + 16, srch + 8);
        asm volatile("cp.async.commit_group;");
    };
    auto compute = [&](int buf) {
        unsigned baseAh = sbase + buf * STG_B;
        unsigned baseAl = baseAh + STG_H * 2;
        unsigned baseBh = baseAh + STG_H * 4;
#pragma unroll
        for (int ks = 0; ks < 32; ks += 16) {
            unsigned ah[4][4], al[4][4];
#pragma unroll
            for (int i = 0; i < 4; i++) {
                unsigned ad = (wm + i * 16) * BSTR * 2 + ks * 2 + offA;
                ldsm_x4(ah[i][0], ah[i][1], ah[i][2], ah[i][3], baseAh + ad);
                ldsm_x4(al[i][0], al[i][1], al[i][2], al[i][3], baseAl + ad);
            }
#pragma unroll
            for (int j = 0; j < 4; j++) {
                unsigned bd = (wn + j * 8) * BSTR * 2 + ks * 2 + offB;
                unsigned bh0, bh1;
                ldsm_x2(bh0, bh1, baseBh + bd);
#pragma unroll
                for (int i = 0; i < 4; i++) {
                    MMA_F16(acc[i][j], ah[i][0], ah[i][1], ah[i][2], ah[i][3], bh0, bh1);
                    MMA_F16(acc[i][j], al[i][0], al[i][1], al[i][2], al[i][3], bh0, bh1);
                }
            }
        }
    };

    // prologue: stage 0
    loadA(0);
    loadB(0, 0);
    storeA(0);
    asm volatile("cp.async.wait_group 0;");
    __syncthreads();

    for (int t = 0; t < nc; t++) {
        int buf = t & 1;
        bool more = (t + 1 < nc);
        if (more) { loadA(t + 1); loadB(t + 1, buf ^ 1); }
        compute(buf);
        if (more) {
            storeA(buf ^ 1);
            asm volatile("cp.async.wait_group 0;");
        }
        __syncthreads();
    }

    // epilogue
#pragma unroll
    for (int i = 0; i < 4; i++) {
        int row0 = m0 + wm + i * 16 + lr;
#pragma unroll
        for (int j = 0; j < 4; j++) {
            int col = n0 + wn + j * 8 + lc * 2;
            float b0 = bias[col], b1 = bias[col + 1];
            float2 v0 = make_float2(acc[i][j][0] + b0, acc[i][j][1] + b1);
            float2 v1 = make_float2(acc[i][j][2] + b0, acc[i][j][3] + b1);
            if (doRelu) {
                v0.x = fmaxf(v0.x, 0.f); v0.y = fmaxf(v0.y, 0.f);
                v1.x = fmaxf(v1.x, 0.f); v1.y = fmaxf(v1.y, 0.f);
            }
            if (row0 < M)     *(float2*)(C + (size_t)row0 * ldc + col) = v0;
            if (row0 + 8 < M) *(float2*)(C + (size_t)(row0 + 8) * ldc + col) = v1;
        }
    }
}

// -------------------------------------------------------------------- pool
__global__ void k_pool() {
    int b = blockIdx.x;
    int f = blockIdx.y * 256 + threadIdx.x;
    int s = g_gptr[b], e = g_gptr[b + 1];
    float m = -FLT_MAX;
    int n = s;
    for (; n + 3 < e; n += 4) {
        float v0 = g_hc[(size_t)(n + 0) * 1024 + f];
        float v1 = g_hc[(size_t)(n + 1) * 1024 + f];
        float v2 = g_hc[(size_t)(n + 2) * 1024 + f];
        float v3 = g_hc[(size_t)(n + 3) * 1024 + f];
        m = fmaxf(m, fmaxf(fmaxf(v0, v1), fmaxf(v2, v3)));
    }
    for (; n < e; n++) m = fmaxf(m, g_hc[(size_t)n * 1024 + f]);
    g_pool[b * 1024 + f] = (e > s) ? m : 0.f;
}

// -------------------------------------------------------------------- head
__global__ void k_head(const float* __restrict__ W1, const float* __restrict__ b1,
                       const float* __restrict__ W2, const float* __restrict__ b2,
                       float* __restrict__ outbuf, int G, int DT) {
    __shared__ float sg[1024];
    __shared__ float sl[256];
    __shared__ float so[32];
    __shared__ float slse;
    int b = blockIdx.x, t = threadIdx.x;
    for (int k = t; k < 1024; k += 256) sg[k] = g_pool[b * 1024 + k];
    __syncthreads();
    float acc = b1[t];
#pragma unroll 4
    for (int k = 0; k < 1024; k++) acc = fmaf(sg[k], W1[k * 256 + t], acc);
    acc = fmaxf(acc, 0.f);
    sl[t] = acc;
    outbuf[2 * G * DT + b * 256 + t] = acc;
    __syncthreads();
    if (t < DT) {
        float o = b2[t];
        for (int k = 0; k < 256; k++) o = fmaf(sl[k], W2[k * DT + t], o);
        so[t] = o;
    }
    __syncthreads();
    if (t == 0) {
        float mx = -FLT_MAX;
        for (int j = 0; j < DT; j++) mx = fmaxf(mx, so[j]);
        float s2 = 0.f;
        for (int j = 0; j < DT; j++) s2 += expf(so[j] - mx);
        slse = mx + logf(s2);
    }
    __syncthreads();
    if (t < DT) {
        outbuf[b * DT + t] = so[t] - slse;
        outbuf[G * DT + b * DT + t] = so[t];
    }
}

// ------------------------------------------------------------------ launch
extern "C" void kernel_launch(void* const* d_in, const int* in_sizes, int n_in,
                              void* d_out, int out_size) {
    const float* x = (const float*)d_in[0];
    const int* ei = (const int*)d_in[1];
    const int* batch = (const int*)d_in[2];
    const float *Wl[4], *bl[4], *Wr[4], *Wm[4], *bm[4];
    int p = 3;
    for (int l = 0; l < 4; l++) {
        Wl[l] = (const float*)d_in[p++];
        bl[l] = (const float*)d_in[p++];
        Wr[l] = (const float*)d_in[p++];
        Wm[l] = (const float*)d_in[p++];
        bm[l] = (const float*)d_in[p++];
    }
    const float* fc1W = (const float*)d_in[p++];
    const float* fc1b = (const float*)d_in[p++];
    const float* fc2W = (const float*)d_in[p++];
    const float* fc2b = (const float*)d_in[p++];

    int N = in_sizes[0] / 128;
    int E = in_sizes[1] / 2;
    int DT = in_sizes[26];
    int G = out_size / (2 * DT + DE);
    int Mb = (N + 127) / 128;

    float *agg, *tmp, *hc;
    int *deg, *rowptr, *cursor, *gcnt, *gptr;
    cudaGetSymbolAddress((void**)&agg, g_agg);
    cudaGetSymbolAddress((void**)&tmp, g_tmp);
    cudaGetSymbolAddress((void**)&hc, g_hc);
    cudaGetSymbolAddress((void**)&deg, g_deg);
    cudaGetSymbolAddress((void**)&rowptr, g_rowptr);
    cudaGetSymbolAddress((void**)&cursor, g_cursor);
    cudaGetSymbolAddress((void**)&gcnt, g_gcnt);
    cudaGetSymbolAddress((void**)&gptr, g_gptr);
    void *pW1h, *pW2h;
    cudaGetSymbolAddress(&pW1h, g_W1h);
    cudaGetSymbolAddress(&pW2h, g_W2h);

    cudaFuncSetAttribute(k_gemm_mma,
                         cudaFuncAttributeMaxDynamicSharedMemorySize, GEMM_SMEM);

    int mx = (N > G) ? N : G;
    k_zero<<<(mx + 255) / 256, 256>>>(N, G);
    k_hist_edges<<<(E + 255) / 256, 256>>>(ei, E, N);
    k_hist_nodes<<<(N + 255) / 256, 256>>>(batch, N, G);
    int nb = (N + 255) / 256;
    k_scan_blk<<<nb, 256>>>(deg, rowptr, N);
    k_scan_top<<<1, 256>>>(nb, rowptr, cursor, N);
    k_scan_add<<<nb, 256>>>(rowptr, cursor, N);
    k_scan<<<1, 1024>>>(gcnt, gptr, gptr, G);
    k_scatter<<<(E + 255) / 256, 256>>>(ei, E, N);

    for (int l = 0; l < 4; l++) {
        int din = l ? 256 : 128;
        int K1 = 2 * din;
        unsigned short* w1h = (unsigned short*)pW1h + (size_t)l * 256 * 512;
        unsigned short* w2h = (unsigned short*)pW2h + (size_t)l * 256 * 256;
        k_wconv<<<(256 * K1 + 255) / 256, 256>>>(Wl[l], din, Wr[l], din, w1h);
        k_wconv<<<(256 * 256 + 255) / 256, 256>>>(Wm[l], 256, nullptr, 0, w2h);
    }

    for (int l = 0; l < 4; l++) {
        const float* h = l ? (hc + (l - 1) * DE) : x;
        int ldh = l ? 1024 : 128;
        int din = l ? 256 : 128;
        unsigned short* w1h = (unsigned short*)pW1h + (size_t)l * 256 * 512;
        unsigned short* w2h = (unsigned short*)pW2h + (size_t)l * 256 * 256;
        k_agg<<<(N * 32 + 255) / 256, 256>>>(h, ldh, din, agg, din, N);
        dim3 gg(Mb, 2);
        k_gemm_mma<<<gg, 256, GEMM_SMEM>>>(agg, din, din, h, ldh, din,
                                           w1h, bl[l], tmp, 256, N, 0);
        k_gemm_mma<<<gg, 256, GEMM_SMEM>>>(tmp, 256, 256, nullptr, 0, 0,
                                           w2h, bm[l], hc + l * DE, 1024, N, 1);
    }
    k_pool<<<dim3(G, 4), 256>>>();
    k_head<<<G, 256>>>(fc1W, fc1b, fc2W, fc2b, (float*)d_out, G, DT);
}

// round 10
// speedup vs baseline: 3.0733x; 1.1720x over previous
#include <cuda_runtime.h>
#include <cuda_fp16.h>
#include <math.h>
#include <float.h>

#define DE 256
#define MAXN 50000
#define MAXG 256
#define MAXE 800000

// ------------------------------------------------------------- scratch
static __device__ int   g_deg[MAXN];
static __device__ int   g_rowptr[MAXN + 1];
static __device__ int   g_cursor[MAXN + 1];
static __device__ int   g_col[MAXE];
static __device__ int   g_gcnt[MAXG];
static __device__ int   g_gptr[MAXG + 1];
static __device__ int   g_part[512];
static __device__ float g_agg[MAXN * 256];
static __device__ float g_tmp[MAXN * 256];
static __device__ float g_hc[(size_t)MAXN * 1024];
static __device__ float g_pool[MAXG * 1024];
// pre-converted weights, fp16 (round-to-nearest), layout [n=256][K]
static __device__ __align__(16) unsigned short g_W1h[4][256 * 512];
static __device__ __align__(16) unsigned short g_W2h[4][256 * 256];

// ---------------------------------------------------------------- utilities
__global__ void k_zero(int N, int G) {
    int i = blockIdx.x * blockDim.x + threadIdx.x;
    if (i < N) g_deg[i] = 0;
    if (i < G) g_gcnt[i] = 0;
}
__device__ __forceinline__ int clampi(int v, int n) {
    return v < 0 ? 0 : (v >= n ? n - 1 : v);
}
__global__ void k_hist_edges(const int* __restrict__ ei, int E, int N) {
    int e = blockIdx.x * blockDim.x + threadIdx.x;
    if (e < E) atomicAdd(&g_deg[clampi(ei[E + e], N)], 1);
}
__global__ void k_hist_nodes(const int* __restrict__ batch, int N, int G) {
    int i = blockIdx.x * blockDim.x + threadIdx.x;
    if (i < N) atomicAdd(&g_gcnt[clampi(batch[i], G)], 1);
}

// three-phase multi-block exclusive scan
__global__ void k_scan_blk(const int* __restrict__ in, int* __restrict__ out, int n) {
    __shared__ int ws[8], wsx[8];
    int i = blockIdx.x * 256 + threadIdx.x;
    int v = (i < n) ? in[i] : 0;
    int lane = threadIdx.x & 31, w = threadIdx.x >> 5;
    int inc = v;
#pragma unroll
    for (int o = 1; o < 32; o <<= 1) {
        int t = __shfl_up_sync(0xffffffffu, inc, o);
        if (lane >= o) inc += t;
    }
    if (lane == 31) ws[w] = inc;
    __syncthreads();
    if (threadIdx.x == 0) {
        int run = 0;
#pragma unroll
        for (int j = 0; j < 8; j++) { int t = ws[j]; wsx[j] = run; run += t; }
        g_part[blockIdx.x] = run;
    }
    __syncthreads();
    if (i < n) out[i] = inc - v + wsx[w];
}
__global__ void k_scan_top(int nb, int* outA, int* outB, int n) {
    __shared__ int ws[8], wsx[8];
    int tid = threadIdx.x;
    int v = (tid < nb) ? g_part[tid] : 0;
    int lane = tid & 31, w = tid >> 5;
    int inc = v;
#pragma unroll
    for (int o = 1; o < 32; o <<= 1) {
        int t = __shfl_up_sync(0xffffffffu, inc, o);
        if (lane >= o) inc += t;
    }
    if (lane == 31) ws[w] = inc;
    __syncthreads();
    if (tid == 0) {
        int run = 0;
#pragma unroll
        for (int j = 0; j < 8; j++) { int t = ws[j]; wsx[j] = run; run += t; }
        outA[n] = run; outB[n] = run;
    }
    __syncthreads();
    int excl = inc - v + wsx[w];
    __syncthreads();
    if (tid < nb) g_part[tid] = excl;
}
__global__ void k_scan_add(int* __restrict__ out, int* __restrict__ out2, int n) {
    int i = blockIdx.x * 256 + threadIdx.x;
    if (i < n) { int v = out[i] + g_part[blockIdx.x]; out[i] = v; out2[i] = v; }
}

__global__ void k_scan(const int* __restrict__ in, int* __restrict__ out,
                       int* __restrict__ out2, int n) {
    __shared__ int wsum[32];
    int tid = threadIdx.x;
    int chunk = (n + blockDim.x - 1) / blockDim.x;
    int s = tid * chunk, e = min(s + chunk, n);
    int local = 0;
    for (int i = s; i < e; i++) local += in[i];
    int lane = tid & 31, wid = tid >> 5;
    int v = local;
#pragma unroll
    for (int o = 1; o < 32; o <<= 1) {
        int t = __shfl_up_sync(0xffffffffu, v, o);
        if (lane >= o) v += t;
    }
    if (lane == 31) wsum[wid] = v;
    __syncthreads();
    if (wid == 0) {
        int nw = blockDim.x >> 5;
        int w = (lane < nw) ? wsum[lane] : 0;
#pragma unroll
        for (int o = 1; o < 32; o <<= 1) {
            int t = __shfl_up_sync(0xffffffffu, w, o);
            if (lane >= o) w += t;
        }
        wsum[lane] = w;
    }
    __syncthreads();
    int excl = v - local + (wid ? wsum[wid - 1] : 0);
    int run = excl;
    for (int i = s; i < e; i++) { out[i] = run; out2[i] = run; run += in[i]; }
    if (s < n && e == n) { out[n] = run; out2[n] = run; }
}

__global__ void k_scatter(const int* __restrict__ ei, int E, int N) {
    int e = blockIdx.x * blockDim.x + threadIdx.x;
    if (e < E) {
        int d = clampi(ei[E + e], N);
        int p = atomicAdd(&g_cursor[d], 1);
        if (p < MAXE) g_col[p] = clampi(ei[e], N);
    }
}

// -------------------------------------------------------------- aggregation
__device__ __forceinline__ float4 fmax4(float4 a, float4 b) {
    return make_float4(fmaxf(a.x, b.x), fmaxf(a.y, b.y),
                       fmaxf(a.z, b.z), fmaxf(a.w, b.w));
}
__global__ void k_agg(const float* __restrict__ h, int ldh, int din,
                      float* __restrict__ out, int ldo, int N) {
    int w = (blockIdx.x * blockDim.x + threadIdx.x) >> 5;
    int lane = threadIdx.x & 31;
    if (w >= N) return;
    int s = g_rowptr[w], e = g_rowptr[w + 1];
    float4 m0 = make_float4(-FLT_MAX, -FLT_MAX, -FLT_MAX, -FLT_MAX);
    float4 m1 = m0;
    if (din == 256) {
        int j = s;
        for (; j + 1 < e; j += 2) {
            const float4* r0 = (const float4*)(h + (size_t)g_col[j] * ldh);
            const float4* r1 = (const float4*)(h + (size_t)g_col[j + 1] * ldh);
            float4 a0 = r0[lane], a1 = r0[lane + 32];
            float4 b0 = r1[lane], b1 = r1[lane + 32];
            m0 = fmax4(m0, fmax4(a0, b0));
            m1 = fmax4(m1, fmax4(a1, b1));
        }
        if (j < e) {
            const float4* r = (const float4*)(h + (size_t)g_col[j] * ldh);
            m0 = fmax4(m0, r[lane]);
            m1 = fmax4(m1, r[lane + 32]);
        }
    } else {
        int j = s;
        for (; j + 1 < e; j += 2) {
            const float4* r0 = (const float4*)(h + (size_t)g_col[j] * ldh);
            const float4* r1 = (const float4*)(h + (size_t)g_col[j + 1] * ldh);
            m0 = fmax4(m0, fmax4(r0[lane], r1[lane]));
        }
        if (j < e) {
            const float4* r = (const float4*)(h + (size_t)g_col[j] * ldh);
            m0 = fmax4(m0, r[lane]);
        }
    }
    if (e == s) { m0 = make_float4(0.f, 0.f, 0.f, 0.f); m1 = m0; }
    float4* o = (float4*)(out + (size_t)w * ldo);
    o[lane] = m0;
    if (din == 256) o[lane + 32] = m1;
}

// ------------------------------------------------------ weight pre-convert
// dst layout [n=256][K] fp16; k < K0 from W0[k][n], else W1[k-K0][n]
__global__ void k_wconv(const float* __restrict__ W0, int K0,
                        const float* __restrict__ W1, int K2,
                        unsigned short* __restrict__ dh) {
    int K = K0 + K2;
    int idx = blockIdx.x * 256 + threadIdx.x;
    if (idx >= 256 * K) return;
    int n = idx / K, k = idx - n * K;
    float f = (k < K0) ? W0[(size_t)k * 256 + n] : W1[(size_t)(k - K0) * 256 + n];
    dh[idx] = __half_as_ushort(__float2half_rn(f));
}

// ------------------------------------------------------- mma.sync fp16 GEMM
// C[M,256] = [A1 | A2] @ W + bias (optional relu), W pre-rounded fp16 [256][K].
// Single-term fp16: C = fp16(A) * fp16(B), fp32 accumulate.
// CTA 128x128, 8 warps 64x32, K-chunk 32, ldmatrix, double-buffered smem,
// cp.async for B, register-prefetch for A.
#define BSTR 40                 // smem halves per row (32 data + 8 pad)
#define STG_H (128 * BSTR)      // halves per array (5120)
#define STG_B (2 * STG_H * 2)   // bytes per stage: Ah, Bh (20480)
#define GEMM_SMEM (2 * STG_B)   // 40960

__device__ __forceinline__ unsigned smem_u32(const void* p) {
    unsigned a;
    asm("{ .reg .u64 t; cvta.to.shared.u64 t, %1; cvt.u32.u64 %0, t; }"
        : "=r"(a) : "l"(p));
    return a;
}
__device__ __forceinline__ unsigned pack_f16(float f0, float f1) {
    unsigned short h0 = __half_as_ushort(__float2half_rn(f0));
    unsigned short h1 = __half_as_ushort(__float2half_rn(f1));
    return (unsigned)h0 | ((unsigned)h1 << 16);
}
__device__ __forceinline__ void ldsm_x4(unsigned& r0, unsigned& r1,
                                        unsigned& r2, unsigned& r3, unsigned a) {
    asm volatile("ldmatrix.sync.aligned.m8n8.x4.shared.b16 {%0,%1,%2,%3}, [%4];"
                 : "=r"(r0), "=r"(r1), "=r"(r2), "=r"(r3) : "r"(a));
}
__device__ __forceinline__ void ldsm_x2(unsigned& r0, unsigned& r1, unsigned a) {
    asm volatile("ldmatrix.sync.aligned.m8n8.x2.shared.b16 {%0,%1}, [%2];"
                 : "=r"(r0), "=r"(r1) : "r"(a));
}
__device__ __forceinline__ void cp16(unsigned dst, const void* src) {
    asm volatile("cp.async.cg.shared.global [%0], [%1], 16;"
                 :: "r"(dst), "l"(src));
}
#define MMA_F16(c, a0, a1, a2, a3, b0, b1)                                    \
    asm volatile(                                                             \
        "mma.sync.aligned.m16n8k16.row.col.f32.f16.f16.f32 "                  \
        "{%0,%1,%2,%3}, {%4,%5,%6,%7}, {%8,%9}, {%0,%1,%2,%3};"               \
        : "+f"((c)[0]), "+f"((c)[1]), "+f"((c)[2]), "+f"((c)[3])              \
        : "r"(a0), "r"(a1), "r"(a2), "r"(a3), "r"(b0), "r"(b1))

__global__ __launch_bounds__(256, 2)
void k_gemm_mma(const float* __restrict__ A1, int lda1, int K0,
                const float* __restrict__ A2, int lda2, int K2,
                const unsigned short* __restrict__ Wh,
                const float* __restrict__ bias,
                float* __restrict__ C, int ldc, int M, int doRelu) {
    extern __shared__ __align__(16) unsigned short sm[];

    const int tid = threadIdx.x;
    const int wid = tid >> 5, lane = tid & 31;
    const int lr = lane >> 2, lc = lane & 3;
    const int m0 = blockIdx.x * 128, n0 = blockIdx.y * 128;
    const int wm = (wid >> 2) * 64, wn = (wid & 3) * 32;
    const int K = K0 + K2;
    const int nc = K >> 5;

    const unsigned sbase = smem_u32(sm);
    const unsigned offA = ((lane & 15) * BSTR + ((lane >> 4) << 3)) * 2;
    const unsigned offB = ((lane & 7) * BSTR + (((lane >> 3) & 1) << 3)) * 2;

    float acc[4][4][4];
#pragma unroll
    for (int i = 0; i < 4; i++)
#pragma unroll
        for (int j = 0; j < 4; j++)
#pragma unroll
            for (int q = 0; q < 4; q++) acc[i][j][q] = 0.f;

    const int s_arow = tid >> 3;          // 0..31
    const int s_akq = (tid & 7) << 2;     // 0,4,..,28
    const int s_br = tid >> 1;            // 0..127
    const int s_bp = (tid & 1) << 4;      // 0 or 16 halves

    float4 av[4];

    auto loadA = [&](int t) {
        int kb = t << 5;
        const float* Asel;
        int lda, kloc;
        if (kb < K0) { Asel = A1; lda = lda1; kloc = kb; }
        else         { Asel = A2; lda = lda2; kloc = kb - K0; }
#pragma unroll
        for (int it = 0; it < 4; it++) {
            int m = m0 + s_arow + it * 32;
            av[it] = (m < M)
                ? *(const float4*)(Asel + (size_t)m * lda + kloc + s_akq)
                : make_float4(0.f, 0.f, 0.f, 0.f);
        }
    };
    auto storeA = [&](int buf) {
        unsigned short* Ah = sm + buf * (2 * STG_H);
#pragma unroll
        for (int it = 0; it < 4; it++) {
            unsigned h0 = pack_f16(av[it].x, av[it].y);
            unsigned h1 = pack_f16(av[it].z, av[it].w);
            int idx = (s_arow + it * 32) * BSTR + s_akq;
            *(uint2*)&Ah[idx] = make_uint2(h0, h1);
        }
    };
    auto loadB = [&](int t, int buf) {
        int kb = t << 5;
        unsigned bh = sbase + buf * STG_B + 2u * STG_H +
                      (s_br * BSTR + s_bp) * 2;
        const unsigned short* srch = Wh + (size_t)(n0 + s_br) * K + kb + s_bp;
        cp16(bh, srch);
        cp16(bh + 16, srch + 8);
        asm volatile("cp.async.commit_group;");
    };
    auto compute = [&](int buf) {
        unsigned baseAh = sbase + buf * STG_B;
        unsigned baseBh = baseAh + STG_H * 2;
#pragma unroll
        for (int ks = 0; ks < 32; ks += 16) {
            unsigned ah[4][4];
#pragma unroll
            for (int i = 0; i < 4; i++) {
                unsigned ad = (wm + i * 16) * BSTR * 2 + ks * 2 + offA;
                ldsm_x4(ah[i][0], ah[i][1], ah[i][2], ah[i][3], baseAh + ad);
            }
#pragma unroll
            for (int j = 0; j < 4; j++) {
                unsigned bd = (wn + j * 8) * BSTR * 2 + ks * 2 + offB;
                unsigned bh0, bh1;
                ldsm_x2(bh0, bh1, baseBh + bd);
#pragma unroll
                for (int i = 0; i < 4; i++) {
                    MMA_F16(acc[i][j], ah[i][0], ah[i][1], ah[i][2], ah[i][3], bh0, bh1);
                }
            }
        }
    };

    // prologue: stage 0
    loadA(0);
    loadB(0, 0);
    storeA(0);
    asm volatile("cp.async.wait_group 0;");
    __syncthreads();

    for (int t = 0; t < nc; t++) {
        int buf = t & 1;
        bool more = (t + 1 < nc);
        if (more) { loadA(t + 1); loadB(t + 1, buf ^ 1); }
        compute(buf);
        if (more) {
            storeA(buf ^ 1);
            asm volatile("cp.async.wait_group 0;");
        }
        __syncthreads();
    }

    // epilogue
#pragma unroll
    for (int i = 0; i < 4; i++) {
        int row0 = m0 + wm + i * 16 + lr;
#pragma unroll
        for (int j = 0; j < 4; j++) {
            int col = n0 + wn + j * 8 + lc * 2;
            float b0 = bias[col], b1 = bias[col + 1];
            float2 v0 = make_float2(acc[i][j][0] + b0, acc[i][j][1] + b1);
            float2 v1 = make_float2(acc[i][j][2] + b0, acc[i][j][3] + b1);
            if (doRelu) {
                v0.x = fmaxf(v0.x, 0.f); v0.y = fmaxf(v0.y, 0.f);
                v1.x = fmaxf(v1.x, 0.f); v1.y = fmaxf(v1.y, 0.f);
            }
            if (row0 < M)     *(float2*)(C + (size_t)row0 * ldc + col) = v0;
            if (row0 + 8 < M) *(float2*)(C + (size_t)(row0 + 8) * ldc + col) = v1;
        }
    }
}

// -------------------------------------------------------------------- pool
__global__ void k_pool() {
    int b = blockIdx.x;
    int f = blockIdx.y * 256 + threadIdx.x;
    int s = g_gptr[b], e = g_gptr[b + 1];
    float m = -FLT_MAX;
    int n = s;
    for (; n + 3 < e; n += 4) {
        float v0 = g_hc[(size_t)(n + 0) * 1024 + f];
        float v1 = g_hc[(size_t)(n + 1) * 1024 + f];
        float v2 = g_hc[(size_t)(n + 2) * 1024 + f];
        float v3 = g_hc[(size_t)(n + 3) * 1024 + f];
        m = fmaxf(m, fmaxf(fmaxf(v0, v1), fmaxf(v2, v3)));
    }
    for (; n < e; n++) m = fmaxf(m, g_hc[(size_t)n * 1024 + f]);
    g_pool[b * 1024 + f] = (e > s) ? m : 0.f;
}

// -------------------------------------------------------------------- head
__global__ void k_head(const float* __restrict__ W1, const float* __restrict__ b1,
                       const float* __restrict__ W2, const float* __restrict__ b2,
                       float* __restrict__ outbuf, int G, int DT) {
    __shared__ float sg[1024];
    __shared__ float sl[256];
    __shared__ float so[32];
    __shared__ float slse;
    int b = blockIdx.x, t = threadIdx.x;
    for (int k = t; k < 1024; k += 256) sg[k] = g_pool[b * 1024 + k];
    __syncthreads();
    float acc = b1[t];
#pragma unroll 4
    for (int k = 0; k < 1024; k++) acc = fmaf(sg[k], W1[k * 256 + t], acc);
    acc = fmaxf(acc, 0.f);
    sl[t] = acc;
    outbuf[2 * G * DT + b * 256 + t] = acc;
    __syncthreads();
    if (t < DT) {
        float o = b2[t];
        for (int k = 0; k < 256; k++) o = fmaf(sl[k], W2[k * DT + t], o);
        so[t] = o;
    }
    __syncthreads();
    if (t == 0) {
        float mx = -FLT_MAX;
        for (int j = 0; j < DT; j++) mx = fmaxf(mx, so[j]);
        float s2 = 0.f;
        for (int j = 0; j < DT; j++) s2 += expf(so[j] - mx);
        slse = mx + logf(s2);
    }
    __syncthreads();
    if (t < DT) {
        outbuf[b * DT + t] = so[t] - slse;
        outbuf[G * DT + b * DT + t] = so[t];
    }
}

// ------------------------------------------------------------------ launch
extern "C" void kernel_launch(void* const* d_in, const int* in_sizes, int n_in,
                              void* d_out, int out_size) {
    const float* x = (const float*)d_in[0];
    const int* ei = (const int*)d_in[1];
    const int* batch = (const int*)d_in[2];
    const float *Wl[4], *bl[4], *Wr[4], *Wm[4], *bm[4];
    int p = 3;
    for (int l = 0; l < 4; l++) {
        Wl[l] = (const float*)d_in[p++];
        bl[l] = (const float*)d_in[p++];
        Wr[l] = (const float*)d_in[p++];
        Wm[l] = (const float*)d_in[p++];
        bm[l] = (const float*)d_in[p++];
    }
    const float* fc1W = (const float*)d_in[p++];
    const float* fc1b = (const float*)d_in[p++];
    const float* fc2W = (const float*)d_in[p++];
    const float* fc2b = (const float*)d_in[p++];

    int N = in_sizes[0] / 128;
    int E = in_sizes[1] / 2;
    int DT = in_sizes[26];
    int G = out_size / (2 * DT + DE);
    int Mb = (N + 127) / 128;

    float *agg, *tmp, *hc;
    int *deg, *rowptr, *cursor, *gcnt, *gptr;
    cudaGetSymbolAddress((void**)&agg, g_agg);
    cudaGetSymbolAddress((void**)&tmp, g_tmp);
    cudaGetSymbolAddress((void**)&hc, g_hc);
    cudaGetSymbolAddress((void**)&deg, g_deg);
    cudaGetSymbolAddress((void**)&rowptr, g_rowptr);
    cudaGetSymbolAddress((void**)&cursor, g_cursor);
    cudaGetSymbolAddress((void**)&gcnt, g_gcnt);
    cudaGetSymbolAddress((void**)&gptr, g_gptr);
    void *pW1h, *pW2h;
    cudaGetSymbolAddress(&pW1h, g_W1h);
    cudaGetSymbolAddress(&pW2h, g_W2h);

    cudaFuncSetAttribute(k_gemm_mma,
                         cudaFuncAttributeMaxDynamicSharedMemorySize, GEMM_SMEM);

    int mx = (N > G) ? N : G;
    k_zero<<<(mx + 255) / 256, 256>>>(N, G);
    k_hist_edges<<<(E + 255) / 256, 256>>>(ei, E, N);
    k_hist_nodes<<<(N + 255) / 256, 256>>>(batch, N, G);
    int nb = (N + 255) / 256;
    k_scan_blk<<<nb, 256>>>(deg, rowptr, N);
    k_scan_top<<<1, 256>>>(nb, rowptr, cursor, N);
    k_scan_add<<<nb, 256>>>(rowptr, cursor, N);
    k_scan<<<1, 1024>>>(gcnt, gptr, gptr, G);
    k_scatter<<<(E + 255) / 256, 256>>>(ei, E, N);

    for (int l = 0; l < 4; l++) {
        int din = l ? 256 : 128;
        int K1 = 2 * din;
        unsigned short* w1h = (unsigned short*)pW1h + (size_t)l * 256 * 512;
        unsigned short* w2h = (unsigned short*)pW2h + (size_t)l * 256 * 256;
        k_wconv<<<(256 * K1 + 255) / 256, 256>>>(Wl[l], din, Wr[l], din, w1h);
        k_wconv<<<(256 * 256 + 255) / 256, 256>>>(Wm[l], 256, nullptr, 0, w2h);
    }

    for (int l = 0; l < 4; l++) {
        const float* h = l ? (hc + (l - 1) * DE) : x;
        int ldh = l ? 1024 : 128;
        int din = l ? 256 : 128;
        unsigned short* w1h = (unsigned short*)pW1h + (size_t)l * 256 * 512;
        unsigned short* w2h = (unsigned short*)pW2h + (size_t)l * 256 * 256;
        k_agg<<<(N * 32 + 255) / 256, 256>>>(h, ldh, din, agg, din, N);
        dim3 gg(Mb, 2);
        k_gemm_mma<<<gg, 256, GEMM_SMEM>>>(agg, din, din, h, ldh, din,
                                           w1h, bl[l], tmp, 256, N, 0);
        k_gemm_mma<<<gg, 256, GEMM_SMEM>>>(tmp, 256, 256, nullptr, 0, 0,
                                           w2h, bm[l], hc + l * DE, 1024, N, 1);
    }
    k_pool<<<dim3(G, 4), 256>>>();
    k_head<<<G, 256>>>(fc1W, fc1b, fc2W, fc2b, (float*)d_out, G, DT);
}

// round 14
// speedup vs baseline: 3.3585x; 1.0928x over previous
#include <cuda_runtime.h>
#include <cuda_fp16.h>
#include <math.h>
#include <float.h>

#define DE 256
#define MAXN 50000
#define MAXG 256
#define MAXE 800000

// ------------------------------------------------------------- scratch
static __device__ int   g_deg[MAXN];
static __device__ int   g_rowptr[MAXN + 1];
static __device__ int   g_cursor[MAXN + 1];
static __device__ int   g_col[MAXE];
static __device__ int   g_gcnt[MAXG];
static __device__ int   g_gptr[MAXG + 1];
static __device__ int   g_part[512];
static __device__ float g_pool[MAXG * 1024];
// fp16 activations
static __device__ __align__(16) unsigned short g_x16[(size_t)MAXN * 128];
static __device__ __align__(16) unsigned short g_agg16[(size_t)MAXN * 256];
static __device__ __align__(16) unsigned short g_tmp16[(size_t)MAXN * 256];
static __device__ __align__(16) unsigned short g_hc16[(size_t)MAXN * 1024];
// pre-converted weights, fp16, layout [n=256][K]
static __device__ __align__(16) unsigned short g_W1h[4][256 * 512];
static __device__ __align__(16) unsigned short g_W2h[4][256 * 256];

// ---------------------------------------------------------------- utilities
__global__ void k_zero(int N, int G) {
    int i = blockIdx.x * blockDim.x + threadIdx.x;
    if (i < N) g_deg[i] = 0;
    if (i < G) g_gcnt[i] = 0;
}
__device__ __forceinline__ int clampi(int v, int n) {
    return v < 0 ? 0 : (v >= n ? n - 1 : v);
}
__global__ void k_hist_edges(const int* __restrict__ ei, int E, int N) {
    int e = blockIdx.x * blockDim.x + threadIdx.x;
    if (e < E) atomicAdd(&g_deg[clampi(ei[E + e], N)], 1);
}
__global__ void k_hist_nodes(const int* __restrict__ batch, int N, int G) {
    int i = blockIdx.x * blockDim.x + threadIdx.x;
    if (i < N) atomicAdd(&g_gcnt[clampi(batch[i], G)], 1);
}

// convert x to fp16 (monotone rounding: commutes with scatter-max)
__global__ void k_x16(const float* __restrict__ x, int n) {
    int i = blockIdx.x * 256 + threadIdx.x;
    if (i < n) g_x16[i] = __half_as_ushort(__float2half_rn(x[i]));
}

// three-phase multi-block exclusive scan
__global__ void k_scan_blk(const int* __restrict__ in, int* __restrict__ out, int n) {
    __shared__ int ws[8], wsx[8];
    int i = blockIdx.x * 256 + threadIdx.x;
    int v = (i < n) ? in[i] : 0;
    int lane = threadIdx.x & 31, w = threadIdx.x >> 5;
    int inc = v;
#pragma unroll
    for (int o = 1; o < 32; o <<= 1) {
        int t = __shfl_up_sync(0xffffffffu, inc, o);
        if (lane >= o) inc += t;
    }
    if (lane == 31) ws[w] = inc;
    __syncthreads();
    if (threadIdx.x == 0) {
        int run = 0;
#pragma unroll
        for (int j = 0; j < 8; j++) { int t = ws[j]; wsx[j] = run; run += t; }
        g_part[blockIdx.x] = run;
    }
    __syncthreads();
    if (i < n) out[i] = inc - v + wsx[w];
}
__global__ void k_scan_top(int nb, int* outA, int* outB, int n) {
    __shared__ int ws[8], wsx[8];
    int tid = threadIdx.x;
    int v = (tid < nb) ? g_part[tid] : 0;
    int lane = tid & 31, w = tid >> 5;
    int inc = v;
#pragma unroll
    for (int o = 1; o < 32; o <<= 1) {
        int t = __shfl_up_sync(0xffffffffu, inc, o);
        if (lane >= o) inc += t;
    }
    if (lane == 31) ws[w] = inc;
    __syncthreads();
    if (tid == 0) {
        int run = 0;
#pragma unroll
        for (int j = 0; j < 8; j++) { int t = ws[j]; wsx[j] = run; run += t; }
        outA[n] = run; outB[n] = run;
    }
    __syncthreads();
    int excl = inc - v + wsx[w];
    __syncthreads();
    if (tid < nb) g_part[tid] = excl;
}
__global__ void k_scan_add(int* __restrict__ out, int* __restrict__ out2, int n) {
    int i = blockIdx.x * 256 + threadIdx.x;
    if (i < n) { int v = out[i] + g_part[blockIdx.x]; out[i] = v; out2[i] = v; }
}

__global__ void k_scan(const int* __restrict__ in, int* __restrict__ out,
                       int* __restrict__ out2, int n) {
    __shared__ int wsum[32];
    int tid = threadIdx.x;
    int chunk = (n + blockDim.x - 1) / blockDim.x;
    int s = tid * chunk, e = min(s + chunk, n);
    int local = 0;
    for (int i = s; i < e; i++) local += in[i];
    int lane = tid & 31, wid = tid >> 5;
    int v = local;
#pragma unroll
    for (int o = 1; o < 32; o <<= 1) {
        int t = __shfl_up_sync(0xffffffffu, v, o);
        if (lane >= o) v += t;
    }
    if (lane == 31) wsum[wid] = v;
    __syncthreads();
    if (wid == 0) {
        int nw = blockDim.x >> 5;
        int w = (lane < nw) ? wsum[lane] : 0;
#pragma unroll
        for (int o = 1; o < 32; o <<= 1) {
            int t = __shfl_up_sync(0xffffffffu, w, o);
            if (lane >= o) w += t;
        }
        wsum[lane] = w;
    }
    __syncthreads();
    int excl = v - local + (wid ? wsum[wid - 1] : 0);
    int run = excl;
    for (int i = s; i < e; i++) { out[i] = run; out2[i] = run; run += in[i]; }
    if (s < n && e == n) { out[n] = run; out2[n] = run; }
}

__global__ void k_scatter(const int* __restrict__ ei, int E, int N) {
    int e = blockIdx.x * blockDim.x + threadIdx.x;
    if (e < E) {
        int d = clampi(ei[E + e], N);
        int p = atomicAdd(&g_cursor[d], 1);
        if (p < MAXE) g_col[p] = clampi(ei[e], N);
    }
}

// --------------------------------------------------- fp16 aggregation (max)
__global__ void k_agg16(const unsigned short* __restrict__ h, int ldh, int din,
                        unsigned short* __restrict__ out, int ldo, int N) {
    int w = (blockIdx.x * blockDim.x + threadIdx.x) >> 5;
    int lane = threadIdx.x & 31;
    if (w >= N) return;
    int s = g_rowptr[w], e = g_rowptr[w + 1];
    const unsigned NEG = 0xFC00FC00u;           // half2(-inf,-inf)
    __half2 m0 = *(__half2*)&NEG, m1 = m0, m2 = m0, m3 = m0;
    if (din == 256) {
        int j = s;
        for (; j + 1 < e; j += 2) {
            const uint4* r0 = (const uint4*)(h + (size_t)g_col[j] * ldh);
            const uint4* r1 = (const uint4*)(h + (size_t)g_col[j + 1] * ldh);
            uint4 a = r0[lane], b = r1[lane];
            m0 = __hmax2(m0, __hmax2(*(__half2*)&a.x, *(__half2*)&b.x));
            m1 = __hmax2(m1, __hmax2(*(__half2*)&a.y, *(__half2*)&b.y));
            m2 = __hmax2(m2, __hmax2(*(__half2*)&a.z, *(__half2*)&b.z));
            m3 = __hmax2(m3, __hmax2(*(__half2*)&a.w, *(__half2*)&b.w));
        }
        if (j < e) {
            uint4 a = ((const uint4*)(h + (size_t)g_col[j] * ldh))[lane];
            m0 = __hmax2(m0, *(__half2*)&a.x);
            m1 = __hmax2(m1, *(__half2*)&a.y);
            m2 = __hmax2(m2, *(__half2*)&a.z);
            m3 = __hmax2(m3, *(__half2*)&a.w);
        }
        if (e == s) { unsigned z = 0; m0 = *(__half2*)&z; m1 = m0; m2 = m0; m3 = m0; }
        uint4 o;
        o.x = *(unsigned*)&m0; o.y = *(unsigned*)&m1;
        o.z = *(unsigned*)&m2; o.w = *(unsigned*)&m3;
        ((uint4*)(out + (size_t)w * ldo))[lane] = o;
    } else {   // din == 128: uint2 (4 halves) per lane
        int j = s;
        for (; j + 1 < e; j += 2) {
            const uint2* r0 = (const uint2*)(h + (size_t)g_col[j] * ldh);
            const uint2* r1 = (const uint2*)(h + (size_t)g_col[j + 1] * ldh);
            uint2 a = r0[lane], b = r1[lane];
            m0 = __hmax2(m0, __hmax2(*(__half2*)&a.x, *(__half2*)&b.x));
            m1 = __hmax2(m1, __hmax2(*(__half2*)&a.y, *(__half2*)&b.y));
        }
        if (j < e) {
            uint2 a = ((const uint2*)(h + (size_t)g_col[j] * ldh))[lane];
            m0 = __hmax2(m0, *(__half2*)&a.x);
            m1 = __hmax2(m1, *(__half2*)&a.y);
        }
        if (e == s) { unsigned z = 0; m0 = *(__half2*)&z; m1 = m0; }
        uint2 o;
        o.x = *(unsigned*)&m0; o.y = *(unsigned*)&m1;
        ((uint2*)(out + (size_t)w * ldo))[lane] = o;
    }
}

// ------------------------------------------------------ weight pre-convert
// dst layout [n=256][K] fp16; k < K0 from W0[k][n], else W1[k-K0][n]
__global__ void k_wconv(const float* __restrict__ W0, int K0,
                        const float* __restrict__ W1, int K2,
                        unsigned short* __restrict__ dh) {
    int K = K0 + K2;
    int idx = blockIdx.x * 256 + threadIdx.x;
    if (idx >= 256 * K) return;
    int n = idx / K, k = idx - n * K;
    float f = (k < K0) ? W0[(size_t)k * 256 + n] : W1[(size_t)(k - K0) * 256 + n];
    dh[idx] = __half_as_ushort(__float2half_rn(f));
}

// ------------------------------------------------------- mma.sync fp16 GEMM
// C16[M,256] = [A1 | A2] @ W + bias (optional relu); all operands fp16,
// fp32 accumulate, output rounded to fp16.
// CTA 128x128, 8 warps 64x32, K-chunk 32, ldmatrix, double-buffered smem,
// cp.async for BOTH A and B (no conversion in kernel).
#define BSTR 40                 // smem halves per row (32 data + 8 pad)
#define STG_H (128 * BSTR)      // halves per array (5120)
#define STG_B (2 * STG_H * 2)   // bytes per stage: A, B (20480)
#define GEMM_SMEM (2 * STG_B)   // 40960

__device__ __forceinline__ unsigned smem_u32(const void* p) {
    unsigned a;
    asm("{ .reg .u64 t; cvta.to.shared.u64 t, %1; cvt.u32.u64 %0, t; }"
        : "=r"(a) : "l"(p));
    return a;
}
__device__ __forceinline__ unsigned pack_f16(float f0, float f1) {
    unsigned short h0 = __half_as_ushort(__float2half_rn(f0));
    unsigned short h1 = __half_as_ushort(__float2half_rn(f1));
    return (unsigned)h0 | ((unsigned)h1 << 16);
}
__device__ __forceinline__ void ldsm_x4(unsigned& r0, unsigned& r1,
                                        unsigned& r2, unsigned& r3, unsigned a) {
    asm volatile("ldmatrix.sync.aligned.m8n8.x4.shared.b16 {%0,%1,%2,%3}, [%4];"
                 : "=r"(r0), "=r"(r1), "=r"(r2), "=r"(r3) : "r"(a));
}
__device__ __forceinline__ void ldsm_x2(unsigned& r0, unsigned& r1, unsigned a) {
    asm volatile("ldmatrix.sync.aligned.m8n8.x2.shared.b16 {%0,%1}, [%2];"
                 : "=r"(r0), "=r"(r1) : "r"(a));
}
__device__ __forceinline__ void cp16(unsigned dst, const void* src) {
    asm volatile("cp.async.cg.shared.global [%0], [%1], 16;"
                 :: "r"(dst), "l"(src));
}
#define MMA_F16(c, a0, a1, a2, a3, b0, b1)                                    \
    asm volatile(                                                             \
        "mma.sync.aligned.m16n8k16.row.col.f32.f16.f16.f32 "                  \
        "{%0,%1,%2,%3}, {%4,%5,%6,%7}, {%8,%9}, {%0,%1,%2,%3};"               \
        : "+f"((c)[0]), "+f"((c)[1]), "+f"((c)[2]), "+f"((c)[3])              \
        : "r"(a0), "r"(a1), "r"(a2), "r"(a3), "r"(b0), "r"(b1))

__global__ __launch_bounds__(256, 2)
void k_gemm_mma(const unsigned short* __restrict__ A1, int lda1, int K0,
                const unsigned short* __restrict__ A2, int lda2, int K2,
                const unsigned short* __restrict__ Wh,
                const float* __restrict__ bias,
                unsigned short* __restrict__ C, int ldc, int M, int doRelu) {
    extern __shared__ __align__(16) unsigned short sm[];

    const int tid = threadIdx.x;
    const int wid = tid >> 5, lane = tid & 31;
    const int lr = lane >> 2, lc = lane & 3;
    const int m0 = blockIdx.x * 128, n0 = blockIdx.y * 128;
    const int wm = (wid >> 2) * 64, wn = (wid & 3) * 32;
    const int K = K0 + K2;
    const int nc = K >> 5;

    const unsigned sbase = smem_u32(sm);
    const unsigned offA = ((lane & 15) * BSTR + ((lane >> 4) << 3)) * 2;
    const unsigned offB = ((lane & 7) * BSTR + (((lane >> 3) & 1) << 3)) * 2;

    float acc[4][4][4];
#pragma unroll
    for (int i = 0; i < 4; i++)
#pragma unroll
        for (int j = 0; j < 4; j++)
#pragma unroll
            for (int q = 0; q < 4; q++) acc[i][j][q] = 0.f;

    const int s_ar = tid >> 1;            // 0..127 (row for A and B staging)
    const int s_ap = (tid & 1) << 4;      // 0 or 16 halves

    // clamped A row (rows >= M load valid data whose outputs are discarded)
    int am = m0 + s_ar; if (am >= M) am = M - 1;

    auto loadAB = [&](int t, int buf) {
        int kb = t << 5;
        const unsigned short* Asel;
        int lda, kloc;
        if (kb < K0) { Asel = A1; lda = lda1; kloc = kb; }
        else         { Asel = A2; lda = lda2; kloc = kb - K0; }
        // A: each thread covers halves [s_ap, s_ap+16) of its row
        unsigned ad = sbase + buf * STG_B + (s_ar * BSTR + s_ap) * 2;
        const unsigned short* asrc = Asel + (size_t)am * lda + kloc + s_ap;
        cp16(ad, asrc);
        cp16(ad + 16, asrc + 8);
        // B: same coverage
        unsigned bd = sbase + buf * STG_B + 2u * STG_H + (s_ar * BSTR + s_ap) * 2;
        const unsigned short* bsrc = Wh + (size_t)(n0 + s_ar) * K + kb + s_ap;
        cp16(bd, bsrc);
        cp16(bd + 16, bsrc + 8);
        asm volatile("cp.async.commit_group;");
    };
    auto compute = [&](int buf) {
        unsigned baseA = sbase + buf * STG_B;
        unsigned baseB = baseA + STG_H * 2;
#pragma unroll
        for (int ks = 0; ks < 32; ks += 16) {
            unsigned ah[4][4];
#pragma unroll
            for (int i = 0; i < 4; i++) {
                unsigned ad = (wm + i * 16) * BSTR * 2 + ks * 2 + offA;
                ldsm_x4(ah[i][0], ah[i][1], ah[i][2], ah[i][3], baseA + ad);
            }
#pragma unroll
            for (int j = 0; j < 4; j++) {
                unsigned bd = (wn + j * 8) * BSTR * 2 + ks * 2 + offB;
                unsigned bh0, bh1;
                ldsm_x2(bh0, bh1, baseB + bd);
#pragma unroll
                for (int i = 0; i < 4; i++) {
                    MMA_F16(acc[i][j], ah[i][0], ah[i][1], ah[i][2], ah[i][3], bh0, bh1);
                }
            }
        }
    };

    // prologue
    loadAB(0, 0);
    asm volatile("cp.async.wait_group 0;");
    __syncthreads();

    for (int t = 0; t < nc; t++) {
        int buf = t & 1;
        bool more = (t + 1 < nc);
        if (more) loadAB(t + 1, buf ^ 1);
        compute(buf);
        if (more) asm volatile("cp.async.wait_group 0;");
        __syncthreads();
    }

    // epilogue: fp32 bias/relu, round to fp16, 32-bit stores
#pragma unroll
    for (int i = 0; i < 4; i++) {
        int row0 = m0 + wm + i * 16 + lr;
#pragma unroll
        for (int j = 0; j < 4; j++) {
            int col = n0 + wn + j * 8 + lc * 2;
            float b0 = bias[col], b1 = bias[col + 1];
            float v00 = acc[i][j][0] + b0, v01 = acc[i][j][1] + b1;
            float v10 = acc[i][j][2] + b0, v11 = acc[i][j][3] + b1;
            if (doRelu) {
                v00 = fmaxf(v00, 0.f); v01 = fmaxf(v01, 0.f);
                v10 = fmaxf(v10, 0.f); v11 = fmaxf(v11, 0.f);
            }
            if (row0 < M)
                *(unsigned*)(C + (size_t)row0 * ldc + col) = pack_f16(v00, v01);
            if (row0 + 8 < M)
                *(unsigned*)(C + (size_t)(row0 + 8) * ldc + col) = pack_f16(v10, v11);
        }
    }
}

// -------------------------------------------------------------------- pool
__global__ void k_pool() {
    int b = blockIdx.x;
    int f = blockIdx.y * 256 + threadIdx.x;
    int s = g_gptr[b], e = g_gptr[b + 1];
    const unsigned short* hc = g_hc16;
    float m = -FLT_MAX;
    int n = s;
    for (; n + 3 < e; n += 4) {
        float v0 = __half2float(__ushort_as_half(hc[(size_t)(n + 0) * 1024 + f]));
        float v1 = __half2float(__ushort_as_half(hc[(size_t)(n + 1) * 1024 + f]));
        float v2 = __half2float(__ushort_as_half(hc[(size_t)(n + 2) * 1024 + f]));
        float v3 = __half2float(__ushort_as_half(hc[(size_t)(n + 3) * 1024 + f]));
        m = fmaxf(m, fmaxf(fmaxf(v0, v1), fmaxf(v2, v3)));
    }
    for (; n < e; n++)
        m = fmaxf(m, __half2float(__ushort_as_half(hc[(size_t)n * 1024 + f])));
    g_pool[b * 1024 + f] = (e > s) ? m : 0.f;
}

// -------------------------------------------------------------------- head
__global__ void k_head(const float* __restrict__ W1, const float* __restrict__ b1,
                       const float* __restrict__ W2, const float* __restrict__ b2,
                       float* __restrict__ outbuf, int G, int DT) {
    __shared__ float sg[1024];
    __shared__ float sl[256];
    __shared__ float so[32];
    __shared__ float slse;
    int b = blockIdx.x, t = threadIdx.x;
    for (int k = t; k < 1024; k += 256) sg[k] = g_pool[b * 1024 + k];
    __syncthreads();
    float acc = b1[t];
#pragma unroll 4
    for (int k = 0; k < 1024; k++) acc = fmaf(sg[k], W1[k * 256 + t], acc);
    acc = fmaxf(acc, 0.f);
    sl[t] = acc;
    outbuf[2 * G * DT + b * 256 + t] = acc;
    __syncthreads();
    if (t < DT) {
        float o = b2[t];
        for (int k = 0; k < 256; k++) o = fmaf(sl[k], W2[k * DT + t], o);
        so[t] = o;
    }
    __syncthreads();
    if (t == 0) {
        float mx = -FLT_MAX;
        for (int j = 0; j < DT; j++) mx = fmaxf(mx, so[j]);
        float s2 = 0.f;
        for (int j = 0; j < DT; j++) s2 += expf(so[j] - mx);
        slse = mx + logf(s2);
    }
    __syncthreads();
    if (t < DT) {
        outbuf[b * DT + t] = so[t] - slse;
        outbuf[G * DT + b * DT + t] = so[t];
    }
}

// ------------------------------------------------------------------ launch
extern "C" void kernel_launch(void* const* d_in, const int* in_sizes, int n_in,
                              void* d_out, int out_size) {
    const float* x = (const float*)d_in[0];
    const int* ei = (const int*)d_in[1];
    const int* batch = (const int*)d_in[2];
    const float *Wl[4], *bl[4], *Wr[4], *Wm[4], *bm[4];
    int p = 3;
    for (int l = 0; l < 4; l++) {
        Wl[l] = (const float*)d_in[p++];
        bl[l] = (const float*)d_in[p++];
        Wr[l] = (const float*)d_in[p++];
        Wm[l] = (const float*)d_in[p++];
        bm[l] = (const float*)d_in[p++];
    }
    const float* fc1W = (const float*)d_in[p++];
    const float* fc1b = (const float*)d_in[p++];
    const float* fc2W = (const float*)d_in[p++];
    const float* fc2b = (const float*)d_in[p++];

    int N = in_sizes[0] / 128;
    int E = in_sizes[1] / 2;
    int DT = in_sizes[26];
    int G = out_size / (2 * DT + DE);
    int Mb = (N + 127) / 128;

    int *deg, *rowptr, *cursor, *gcnt, *gptr;
    cudaGetSymbolAddress((void**)&deg, g_deg);
    cudaGetSymbolAddress((void**)&rowptr, g_rowptr);
    cudaGetSymbolAddress((void**)&cursor, g_cursor);
    cudaGetSymbolAddress((void**)&gcnt, g_gcnt);
    cudaGetSymbolAddress((void**)&gptr, g_gptr);
    void *px16, *pagg, *ptmp, *phc, *pW1h, *pW2h;
    cudaGetSymbolAddress(&px16, g_x16);
    cudaGetSymbolAddress(&pagg, g_agg16);
    cudaGetSymbolAddress(&ptmp, g_tmp16);
    cudaGetSymbolAddress(&phc, g_hc16);
    cudaGetSymbolAddress(&pW1h, g_W1h);
    cudaGetSymbolAddress(&pW2h, g_W2h);
    unsigned short* x16 = (unsigned short*)px16;
    unsigned short* agg16 = (unsigned short*)pagg;
    unsigned short* tmp16 = (unsigned short*)ptmp;
    unsigned short* hc16 = (unsigned short*)phc;

    cudaFuncSetAttribute(k_gemm_mma,
                         cudaFuncAttributeMaxDynamicSharedMemorySize, GEMM_SMEM);

    int mx = (N > G) ? N : G;
    k_zero<<<(mx + 255) / 256, 256>>>(N, G);
    k_hist_edges<<<(E + 255) / 256, 256>>>(ei, E, N);
    k_hist_nodes<<<(N + 255) / 256, 256>>>(batch, N, G);
    int nb = (N + 255) / 256;
    k_scan_blk<<<nb, 256>>>(deg, rowptr, N);
    k_scan_top<<<1, 256>>>(nb, rowptr, cursor, N);
    k_scan_add<<<nb, 256>>>(rowptr, cursor, N);
    k_scan<<<1, 1024>>>(gcnt, gptr, gptr, G);
    k_scatter<<<(E + 255) / 256, 256>>>(ei, E, N);
    k_x16<<<(N * 128 + 255) / 256, 256>>>(x, N * 128);

    for (int l = 0; l < 4; l++) {
        int din = l ? 256 : 128;
        int K1 = 2 * din;
        unsigned short* w1h = (unsigned short*)pW1h + (size_t)l * 256 * 512;
        unsigned short* w2h = (unsigned short*)pW2h + (size_t)l * 256 * 256;
        k_wconv<<<(256 * K1 + 255) / 256, 256>>>(Wl[l], din, Wr[l], din, w1h);
        k_wconv<<<(256 * 256 + 255) / 256, 256>>>(Wm[l], 256, nullptr, 0, w2h);
    }

    for (int l = 0; l < 4; l++) {
        const unsigned short* h = l ? (hc16 + (l - 1) * DE) : x16;
        int ldh = l ? 1024 : 128;
        int din = l ? 256 : 128;
        unsigned short* w1h = (unsigned short*)pW1h + (size_t)l * 256 * 512;
        unsigned short* w2h = (unsigned short*)pW2h + (size_t)l * 256 * 256;
        k_agg16<<<(N * 32 + 255) / 256, 256>>>(h, ldh, din, agg16, din, N);
        dim3 gg(Mb, 2);
        k_gemm_mma<<<gg, 256, GEMM_SMEM>>>(agg16, din, din, h, ldh, din,
                                           w1h, bl[l], tmp16, 256, N, 0);
        k_gemm_mma<<<gg, 256, GEMM_SMEM>>>(tmp16, 256, 256, nullptr, 0, 0,
                                           w2h, bm[l], hc16 + l * DE, 1024, N, 1);
    }
    k_pool<<<dim3(G, 4), 256>>>();
    k_head<<<G, 256>>>(fc1W, fc1b, fc2W, fc2b, (float*)d_out, G, DT);
}

// round 16
// speedup vs baseline: 3.5313x; 1.0514x over previous
#include <cuda_runtime.h>
#include <cuda_fp16.h>
#include <math.h>
#include <float.h>

#define DE 256
#define MAXN 50000
#define MAXG 256
#define MAXE 800000

// ------------------------------------------------------------- scratch
static __device__ int   g_deg[MAXN];
static __device__ int   g_rowptr[MAXN + 1];
static __device__ int   g_cursor[MAXN + 1];
static __device__ int   g_col[MAXE];
static __device__ int   g_gcnt[MAXG];
static __device__ int   g_gptr[MAXG + 1];
static __device__ int   g_part[512];
static __device__ float g_pool[MAXG * 1024];
// fp16 activations
static __device__ __align__(16) unsigned short g_x16[(size_t)MAXN * 128];
static __device__ __align__(16) unsigned short g_agg16[(size_t)MAXN * 256];
static __device__ __align__(16) unsigned short g_tmp16[(size_t)MAXN * 256];
static __device__ __align__(16) unsigned short g_hc16[(size_t)MAXN * 1024];
// pre-converted weights, fp16, layout [n=256][K]
static __device__ __align__(16) unsigned short g_W1h[4][256 * 512];
static __device__ __align__(16) unsigned short g_W2h[4][256 * 256];

// ---------------------------------------------------------------- utilities
__global__ void k_zero(int N, int G) {
    int i = blockIdx.x * blockDim.x + threadIdx.x;
    if (i < N) g_deg[i] = 0;
    if (i < G) g_gcnt[i] = 0;
}
__device__ __forceinline__ int clampi(int v, int n) {
    return v < 0 ? 0 : (v >= n ? n - 1 : v);
}
__global__ void k_hist_edges(const int* __restrict__ ei, int E, int N) {
    int e = blockIdx.x * blockDim.x + threadIdx.x;
    if (e < E) atomicAdd(&g_deg[clampi(ei[E + e], N)], 1);
}
__global__ void k_hist_nodes(const int* __restrict__ batch, int N, int G) {
    int i = blockIdx.x * blockDim.x + threadIdx.x;
    if (i < N) atomicAdd(&g_gcnt[clampi(batch[i], G)], 1);
}

// convert x to fp16 (monotone rounding: commutes with scatter-max)
__global__ void k_x16(const float* __restrict__ x, int n) {
    int i = blockIdx.x * 256 + threadIdx.x;
    if (i < n) g_x16[i] = __half_as_ushort(__float2half_rn(x[i]));
}

// three-phase multi-block exclusive scan
__global__ void k_scan_blk(const int* __restrict__ in, int* __restrict__ out, int n) {
    __shared__ int ws[8], wsx[8];
    int i = blockIdx.x * 256 + threadIdx.x;
    int v = (i < n) ? in[i] : 0;
    int lane = threadIdx.x & 31, w = threadIdx.x >> 5;
    int inc = v;
#pragma unroll
    for (int o = 1; o < 32; o <<= 1) {
        int t = __shfl_up_sync(0xffffffffu, inc, o);
        if (lane >= o) inc += t;
    }
    if (lane == 31) ws[w] = inc;
    __syncthreads();
    if (threadIdx.x == 0) {
        int run = 0;
#pragma unroll
        for (int j = 0; j < 8; j++) { int t = ws[j]; wsx[j] = run; run += t; }
        g_part[blockIdx.x] = run;
    }
    __syncthreads();
    if (i < n) out[i] = inc - v + wsx[w];
}
__global__ void k_scan_top(int nb, int* outA, int* outB, int n) {
    __shared__ int ws[8], wsx[8];
    int tid = threadIdx.x;
    int v = (tid < nb) ? g_part[tid] : 0;
    int lane = tid & 31, w = tid >> 5;
    int inc = v;
#pragma unroll
    for (int o = 1; o < 32; o <<= 1) {
        int t = __shfl_up_sync(0xffffffffu, inc, o);
        if (lane >= o) inc += t;
    }
    if (lane == 31) ws[w] = inc;
    __syncthreads();
    if (tid == 0) {
        int run = 0;
#pragma unroll
        for (int j = 0; j < 8; j++) { int t = ws[j]; wsx[j] = run; run += t; }
        outA[n] = run; outB[n] = run;
    }
    __syncthreads();
    int excl = inc - v + wsx[w];
    __syncthreads();
    if (tid < nb) g_part[tid] = excl;
}
__global__ void k_scan_add(int* __restrict__ out, int* __restrict__ out2, int n) {
    int i = blockIdx.x * 256 + threadIdx.x;
    if (i < n) { int v = out[i] + g_part[blockIdx.x]; out[i] = v; out2[i] = v; }
}

__global__ void k_scan(const int* __restrict__ in, int* __restrict__ out,
                       int* __restrict__ out2, int n) {
    __shared__ int wsum[32];
    int tid = threadIdx.x;
    int chunk = (n + blockDim.x - 1) / blockDim.x;
    int s = tid * chunk, e = min(s + chunk, n);
    int local = 0;
    for (int i = s; i < e; i++) local += in[i];
    int lane = tid & 31, wid = tid >> 5;
    int v = local;
#pragma unroll
    for (int o = 1; o < 32; o <<= 1) {
        int t = __shfl_up_sync(0xffffffffu, v, o);
        if (lane >= o) v += t;
    }
    if (lane == 31) wsum[wid] = v;
    __syncthreads();
    if (wid == 0) {
        int nw = blockDim.x >> 5;
        int w = (lane < nw) ? wsum[lane] : 0;
#pragma unroll
        for (int o = 1; o < 32; o <<= 1) {
            int t = __shfl_up_sync(0xffffffffu, w, o);
            if (lane >= o) w += t;
        }
        wsum[lane] = w;
    }
    __syncthreads();
    int excl = v - local + (wid ? wsum[wid - 1] : 0);
    int run = excl;
    for (int i = s; i < e; i++) { out[i] = run; out2[i] = run; run += in[i]; }
    if (s < n && e == n) { out[n] = run; out2[n] = run; }
}

__global__ void k_scatter(const int* __restrict__ ei, int E, int N) {
    int e = blockIdx.x * blockDim.x + threadIdx.x;
    if (e < E) {
        int d = clampi(ei[E + e], N);
        int p = atomicAdd(&g_cursor[d], 1);
        if (p < MAXE) g_col[p] = clampi(ei[e], N);
    }
}

// --------------------------------------------------- fp16 aggregation (max)
__global__ void k_agg16(const unsigned short* __restrict__ h, int ldh, int din,
                        unsigned short* __restrict__ out, int ldo, int N) {
    int w = (blockIdx.x * blockDim.x + threadIdx.x) >> 5;
    int lane = threadIdx.x & 31;
    if (w >= N) return;
    int s = g_rowptr[w], e = g_rowptr[w + 1];
    const unsigned NEG = 0xFC00FC00u;           // half2(-inf,-inf)
    __half2 m0 = *(__half2*)&NEG, m1 = m0, m2 = m0, m3 = m0;
    if (din == 256) {
        int j = s;
        for (; j + 1 < e; j += 2) {
            const uint4* r0 = (const uint4*)(h + (size_t)g_col[j] * ldh);
            const uint4* r1 = (const uint4*)(h + (size_t)g_col[j + 1] * ldh);
            uint4 a = r0[lane], b = r1[lane];
            m0 = __hmax2(m0, __hmax2(*(__half2*)&a.x, *(__half2*)&b.x));
            m1 = __hmax2(m1, __hmax2(*(__half2*)&a.y, *(__half2*)&b.y));
            m2 = __hmax2(m2, __hmax2(*(__half2*)&a.z, *(__half2*)&b.z));
            m3 = __hmax2(m3, __hmax2(*(__half2*)&a.w, *(__half2*)&b.w));
        }
        if (j < e) {
            uint4 a = ((const uint4*)(h + (size_t)g_col[j] * ldh))[lane];
            m0 = __hmax2(m0, *(__half2*)&a.x);
            m1 = __hmax2(m1, *(__half2*)&a.y);
            m2 = __hmax2(m2, *(__half2*)&a.z);
            m3 = __hmax2(m3, *(__half2*)&a.w);
        }
        if (e == s) { unsigned z = 0; m0 = *(__half2*)&z; m1 = m0; m2 = m0; m3 = m0; }
        uint4 o;
        o.x = *(unsigned*)&m0; o.y = *(unsigned*)&m1;
        o.z = *(unsigned*)&m2; o.w = *(unsigned*)&m3;
        ((uint4*)(out + (size_t)w * ldo))[lane] = o;
    } else {   // din == 128: uint2 (4 halves) per lane
        int j = s;
        for (; j + 1 < e; j += 2) {
            const uint2* r0 = (const uint2*)(h + (size_t)g_col[j] * ldh);
            const uint2* r1 = (const uint2*)(h + (size_t)g_col[j + 1] * ldh);
            uint2 a = r0[lane], b = r1[lane];
            m0 = __hmax2(m0, __hmax2(*(__half2*)&a.x, *(__half2*)&b.x));
            m1 = __hmax2(m1, __hmax2(*(__half2*)&a.y, *(__half2*)&b.y));
        }
        if (j < e) {
            uint2 a = ((const uint2*)(h + (size_t)g_col[j] * ldh))[lane];
            m0 = __hmax2(m0, *(__half2*)&a.x);
            m1 = __hmax2(m1, *(__half2*)&a.y);
        }
        if (e == s) { unsigned z = 0; m0 = *(__half2*)&z; m1 = m0; }
        uint2 o;
        o.x = *(unsigned*)&m0; o.y = *(unsigned*)&m1;
        ((uint2*)(out + (size_t)w * ldo))[lane] = o;
    }
}

// ------------------------------------------------------ weight pre-convert
// dst layout [n=256][K] fp16; k < K0 from W0[k][n], else W1[k-K0][n]
__global__ void k_wconv(const float* __restrict__ W0, int K0,
                        const float* __restrict__ W1, int K2,
                        unsigned short* __restrict__ dh) {
    int K = K0 + K2;
    int idx = blockIdx.x * 256 + threadIdx.x;
    if (idx >= 256 * K) return;
    int n = idx / K, k = idx - n * K;
    float f = (k < K0) ? W0[(size_t)k * 256 + n] : W1[(size_t)(k - K0) * 256 + n];
    dh[idx] = __half_as_ushort(__float2half_rn(f));
}

// ------------------------------------------------------- mma.sync fp16 GEMM
// C16[M,256] = [A1 | A2] @ W + bias (optional relu); all operands fp16,
// fp32 accumulate, output rounded to fp16.
// CTA 128x128, 8 warps 64x32, K-chunk 32, ldmatrix, THREE-stage cp.async
// ring (wait_group 1 keeps one load in flight behind compute).
#define BSTR 40                 // smem halves per row (32 data + 8 pad)
#define STG_H (128 * BSTR)      // halves per array (5120)
#define STG_B (2 * STG_H * 2)   // bytes per stage: A, B (20480)
#define GEMM_SMEM (3 * STG_B)   // 61440

__device__ __forceinline__ unsigned smem_u32(const void* p) {
    unsigned a;
    asm("{ .reg .u64 t; cvta.to.shared.u64 t, %1; cvt.u32.u64 %0, t; }"
        : "=r"(a) : "l"(p));
    return a;
}
__device__ __forceinline__ unsigned pack_f16(float f0, float f1) {
    unsigned short h0 = __half_as_ushort(__float2half_rn(f0));
    unsigned short h1 = __half_as_ushort(__float2half_rn(f1));
    return (unsigned)h0 | ((unsigned)h1 << 16);
}
__device__ __forceinline__ void ldsm_x4(unsigned& r0, unsigned& r1,
                                        unsigned& r2, unsigned& r3, unsigned a) {
    asm volatile("ldmatrix.sync.aligned.m8n8.x4.shared.b16 {%0,%1,%2,%3}, [%4];"
                 : "=r"(r0), "=r"(r1), "=r"(r2), "=r"(r3) : "r"(a));
}
__device__ __forceinline__ void ldsm_x2(unsigned& r0, unsigned& r1, unsigned a) {
    asm volatile("ldmatrix.sync.aligned.m8n8.x2.shared.b16 {%0,%1}, [%2];"
                 : "=r"(r0), "=r"(r1) : "r"(a));
}
__device__ __forceinline__ void cp16(unsigned dst, const void* src) {
    asm volatile("cp.async.cg.shared.global [%0], [%1], 16;"
                 :: "r"(dst), "l"(src));
}
#define MMA_F16(c, a0, a1, a2, a3, b0, b1)                                    \
    asm volatile(                                                             \
        "mma.sync.aligned.m16n8k16.row.col.f32.f16.f16.f32 "                  \
        "{%0,%1,%2,%3}, {%4,%5,%6,%7}, {%8,%9}, {%0,%1,%2,%3};"               \
        : "+f"((c)[0]), "+f"((c)[1]), "+f"((c)[2]), "+f"((c)[3])              \
        : "r"(a0), "r"(a1), "r"(a2), "r"(a3), "r"(b0), "r"(b1))

__global__ __launch_bounds__(256, 2)
void k_gemm_mma(const unsigned short* __restrict__ A1, int lda1, int K0,
                const unsigned short* __restrict__ A2, int lda2, int K2,
                const unsigned short* __restrict__ Wh,
                const float* __restrict__ bias,
                unsigned short* __restrict__ C, int ldc, int M, int doRelu) {
    extern __shared__ __align__(16) unsigned short sm[];

    const int tid = threadIdx.x;
    const int wid = tid >> 5, lane = tid & 31;
    const int lr = lane >> 2, lc = lane & 3;
    const int m0 = blockIdx.x * 128, n0 = blockIdx.y * 128;
    const int wm = (wid >> 2) * 64, wn = (wid & 3) * 32;
    const int K = K0 + K2;
    const int nc = K >> 5;

    const unsigned sbase = smem_u32(sm);
    const unsigned offA = ((lane & 15) * BSTR + ((lane >> 4) << 3)) * 2;
    const unsigned offB = ((lane & 7) * BSTR + (((lane >> 3) & 1) << 3)) * 2;

    float acc[4][4][4];
#pragma unroll
    for (int i = 0; i < 4; i++)
#pragma unroll
        for (int j = 0; j < 4; j++)
#pragma unroll
            for (int q = 0; q < 4; q++) acc[i][j][q] = 0.f;

    const int s_ar = tid >> 1;            // 0..127 (row for A and B staging)
    const int s_ap = (tid & 1) << 4;      // 0 or 16 halves

    // clamped A row (rows >= M load valid data whose outputs are discarded)
    int am = m0 + s_ar; if (am >= M) am = M - 1;

    auto loadAB = [&](int t, int buf) {
        int kb = t << 5;
        const unsigned short* Asel;
        int lda, kloc;
        if (kb < K0) { Asel = A1; lda = lda1; kloc = kb; }
        else         { Asel = A2; lda = lda2; kloc = kb - K0; }
        unsigned ad = sbase + buf * STG_B + (s_ar * BSTR + s_ap) * 2;
        const unsigned short* asrc = Asel + (size_t)am * lda + kloc + s_ap;
        cp16(ad, asrc);
        cp16(ad + 16, asrc + 8);
        unsigned bd = sbase + buf * STG_B + 2u * STG_H + (s_ar * BSTR + s_ap) * 2;
        const unsigned short* bsrc = Wh + (size_t)(n0 + s_ar) * K + kb + s_ap;
        cp16(bd, bsrc);
        cp16(bd + 16, bsrc + 8);
        asm volatile("cp.async.commit_group;");
    };
    auto compute = [&](int buf) {
        unsigned baseA = sbase + buf * STG_B;
        unsigned baseB = baseA + STG_H * 2;
#pragma unroll
        for (int ks = 0; ks < 32; ks += 16) {
            unsigned ah[4][4];
#pragma unroll
            for (int i = 0; i < 4; i++) {
                unsigned ad = (wm + i * 16) * BSTR * 2 + ks * 2 + offA;
                ldsm_x4(ah[i][0], ah[i][1], ah[i][2], ah[i][3], baseA + ad);
            }
#pragma unroll
            for (int j = 0; j < 4; j++) {
                unsigned bd = (wn + j * 8) * BSTR * 2 + ks * 2 + offB;
                unsigned bh0, bh1;
                ldsm_x2(bh0, bh1, baseB + bd);
#pragma unroll
                for (int i = 0; i < 4; i++) {
                    MMA_F16(acc[i][j], ah[i][0], ah[i][1], ah[i][2], ah[i][3], bh0, bh1);
                }
            }
        }
    };

    // prologue: fill 2 of 3 ring slots
    loadAB(0, 0);
    if (nc > 1) loadAB(1, 1);

    int buf = 0;
    for (int t = 0; t < nc; t++) {
        if (t + 1 < nc) asm volatile("cp.async.wait_group 1;");
        else            asm volatile("cp.async.wait_group 0;");
        __syncthreads();
        compute(buf);
        if (t + 2 < nc) {
            int nb_ = buf + 2; if (nb_ >= 3) nb_ -= 3;
            loadAB(t + 2, nb_);
        }
        buf = (buf + 1 == 3) ? 0 : buf + 1;
    }

    // epilogue: fp32 bias/relu, round to fp16, 32-bit stores
#pragma unroll
    for (int i = 0; i < 4; i++) {
        int row0 = m0 + wm + i * 16 + lr;
#pragma unroll
        for (int j = 0; j < 4; j++) {
            int col = n0 + wn + j * 8 + lc * 2;
            float b0 = bias[col], b1 = bias[col + 1];
            float v00 = acc[i][j][0] + b0, v01 = acc[i][j][1] + b1;
            float v10 = acc[i][j][2] + b0, v11 = acc[i][j][3] + b1;
            if (doRelu) {
                v00 = fmaxf(v00, 0.f); v01 = fmaxf(v01, 0.f);
                v10 = fmaxf(v10, 0.f); v11 = fmaxf(v11, 0.f);
            }
            if (row0 < M)
                *(unsigned*)(C + (size_t)row0 * ldc + col) = pack_f16(v00, v01);
            if (row0 + 8 < M)
                *(unsigned*)(C + (size_t)(row0 + 8) * ldc + col) = pack_f16(v10, v11);
        }
    }
}

// -------------------------------------------------------------------- pool
__global__ void k_pool() {
    int b = blockIdx.x;
    int f = blockIdx.y * 256 + threadIdx.x;
    int s = g_gptr[b], e = g_gptr[b + 1];
    const unsigned short* hc = g_hc16;
    float m = -FLT_MAX;
    int n = s;
    for (; n + 3 < e; n += 4) {
        float v0 = __half2float(__ushort_as_half(hc[(size_t)(n + 0) * 1024 + f]));
        float v1 = __half2float(__ushort_as_half(hc[(size_t)(n + 1) * 1024 + f]));
        float v2 = __half2float(__ushort_as_half(hc[(size_t)(n + 2) * 1024 + f]));
        float v3 = __half2float(__ushort_as_half(hc[(size_t)(n + 3) * 1024 + f]));
        m = fmaxf(m, fmaxf(fmaxf(v0, v1), fmaxf(v2, v3)));
    }
    for (; n < e; n++)
        m = fmaxf(m, __half2float(__ushort_as_half(hc[(size_t)n * 1024 + f])));
    g_pool[b * 1024 + f] = (e > s) ? m : 0.f;
}

// -------------------------------------------------------------------- head
__global__ void k_head(const float* __restrict__ W1, const float* __restrict__ b1,
                       const float* __restrict__ W2, const float* __restrict__ b2,
                       float* __restrict__ outbuf, int G, int DT) {
    __shared__ float sg[1024];
    __shared__ float sl[256];
    __shared__ float so[32];
    __shared__ float slse;
    int b = blockIdx.x, t = threadIdx.x;
    for (int k = t; k < 1024; k += 256) sg[k] = g_pool[b * 1024 + k];
    __syncthreads();
    float acc = b1[t];
#pragma unroll 4
    for (int k = 0; k < 1024; k++) acc = fmaf(sg[k], W1[k * 256 + t], acc);
    acc = fmaxf(acc, 0.f);
    sl[t] = acc;
    outbuf[2 * G * DT + b * 256 + t] = acc;
    __syncthreads();
    if (t < DT) {
        float o = b2[t];
        for (int k = 0; k < 256; k++) o = fmaf(sl[k], W2[k * DT + t], o);
        so[t] = o;
    }
    __syncthreads();
    if (t == 0) {
        float mx = -FLT_MAX;
        for (int j = 0; j < DT; j++) mx = fmaxf(mx, so[j]);
        float s2 = 0.f;
        for (int j = 0; j < DT; j++) s2 += expf(so[j] - mx);
        slse = mx + logf(s2);
    }
    __syncthreads();
    if (t < DT) {
        outbuf[b * DT + t] = so[t] - slse;
        outbuf[G * DT + b * DT + t] = so[t];
    }
}

// ------------------------------------------------------------------ launch
extern "C" void kernel_launch(void* const* d_in, const int* in_sizes, int n_in,
                              void* d_out, int out_size) {
    const float* x = (const float*)d_in[0];
    const int* ei = (const int*)d_in[1];
    const int* batch = (const int*)d_in[2];
    const float *Wl[4], *bl[4], *Wr[4], *Wm[4], *bm[4];
    int p = 3;
    for (int l = 0; l < 4; l++) {
        Wl[l] = (const float*)d_in[p++];
        bl[l] = (const float*)d_in[p++];
        Wr[l] = (const float*)d_in[p++];
        Wm[l] = (const float*)d_in[p++];
        bm[l] = (const float*)d_in[p++];
    }
    const float* fc1W = (const float*)d_in[p++];
    const float* fc1b = (const float*)d_in[p++];
    const float* fc2W = (const float*)d_in[p++];
    const float* fc2b = (const float*)d_in[p++];

    int N = in_sizes[0] / 128;
    int E = in_sizes[1] / 2;
    int DT = in_sizes[26];
    int G = out_size / (2 * DT + DE);
    int Mb = (N + 127) / 128;

    int *deg, *rowptr, *cursor, *gcnt, *gptr;
    cudaGetSymbolAddress((void**)&deg, g_deg);
    cudaGetSymbolAddress((void**)&rowptr, g_rowptr);
    cudaGetSymbolAddress((void**)&cursor, g_cursor);
    cudaGetSymbolAddress((void**)&gcnt, g_gcnt);
    cudaGetSymbolAddress((void**)&gptr, g_gptr);
    void *px16, *pagg, *ptmp, *phc, *pW1h, *pW2h;
    cudaGetSymbolAddress(&px16, g_x16);
    cudaGetSymbolAddress(&pagg, g_agg16);
    cudaGetSymbolAddress(&ptmp, g_tmp16);
    cudaGetSymbolAddress(&phc, g_hc16);
    cudaGetSymbolAddress(&pW1h, g_W1h);
    cudaGetSymbolAddress(&pW2h, g_W2h);
    unsigned short* x16 = (unsigned short*)px16;
    unsigned short* agg16 = (unsigned short*)pagg;
    unsigned short* tmp16 = (unsigned short*)ptmp;
    unsigned short* hc16 = (unsigned short*)phc;

    cudaFuncSetAttribute(k_gemm_mma,
                         cudaFuncAttributeMaxDynamicSharedMemorySize, GEMM_SMEM);

    int mx = (N > G) ? N : G;
    k_zero<<<(mx + 255) / 256, 256>>>(N, G);
    k_hist_edges<<<(E + 255) / 256, 256>>>(ei, E, N);
    k_hist_nodes<<<(N + 255) / 256, 256>>>(batch, N, G);
    int nb = (N + 255) / 256;
    k_scan_blk<<<nb, 256>>>(deg, rowptr, N);
    k_scan_top<<<1, 256>>>(nb, rowptr, cursor, N);
    k_scan_add<<<nb, 256>>>(rowptr, cursor, N);
    k_scan<<<1, 1024>>>(gcnt, gptr, gptr, G);
    k_scatter<<<(E + 255) / 256, 256>>>(ei, E, N);
    k_x16<<<(N * 128 + 255) / 256, 256>>>(x, N * 128);

    for (int l = 0; l < 4; l++) {
        int din = l ? 256 : 128;
        int K1 = 2 * din;
        unsigned short* w1h = (unsigned short*)pW1h + (size_t)l * 256 * 512;
        unsigned short* w2h = (unsigned short*)pW2h + (size_t)l * 256 * 256;
        k_wconv<<<(256 * K1 + 255) / 256, 256>>>(Wl[l], din, Wr[l], din, w1h);
        k_wconv<<<(256 * 256 + 255) / 256, 256>>>(Wm[l], 256, nullptr, 0, w2h);
    }

    for (int l = 0; l < 4; l++) {
        const unsigned short* h = l ? (hc16 + (l - 1) * DE) : x16;
        int ldh = l ? 1024 : 128;
        int din = l ? 256 : 128;
        unsigned short* w1h = (unsigned short*)pW1h + (size_t)l * 256 * 512;
        unsigned short* w2h = (unsigned short*)pW2h + (size_t)l * 256 * 256;
        k_agg16<<<(N * 32 + 255) / 256, 256>>>(h, ldh, din, agg16, din, N);
        dim3 gg(Mb, 2);
        k_gemm_mma<<<gg, 256, GEMM_SMEM>>>(agg16, din, din, h, ldh, din,
                                           w1h, bl[l], tmp16, 256, N, 0);
        k_gemm_mma<<<gg, 256, GEMM_SMEM>>>(tmp16, 256, 256, nullptr, 0, 0,
                                           w2h, bm[l], hc16 + l * DE, 1024, N, 1);
    }
    k_pool<<<dim3(G, 4), 256>>>();
    k_head<<<G, 256>>>(fc1W, fc1b, fc2W, fc2b, (float*)d_out, G, DT);
}